// round 6
// baseline (speedup 1.0000x reference)
#include <cuda_runtime.h>
#include <cuda_fp16.h>
#include <cstdint>

#define N_NODES 50000
#define N_EDGES 800000
#define D_IN    128
#define D_HID   256
#define D_OUT   128

// ---------------------------------------------------------------------------
// Device scratch (no cudaMalloc allowed)
// ---------------------------------------------------------------------------
__device__ float  g_agg   [(size_t)N_NODES * D_IN];
__device__ __half g_xh    [(size_t)N_NODES * D_IN];    // fp16 copy of x (gather)
__device__ __half g_hid_hi[(size_t)N_NODES * D_HID];
__device__ __half g_hid_lo[(size_t)N_NODES * D_HID];
__device__ __half g_b1h   [D_HID * D_IN];              // w1^T fp16 [256,128]
__device__ __half g_b2h   [D_OUT * D_HID];             // w2^T fp16 [128,256]

// ---------------------------------------------------------------------------
// helpers
// ---------------------------------------------------------------------------
__device__ __forceinline__ uint32_t smem_u32(const void* p) {
    uint32_t a;
    asm("{ .reg .u64 t; cvta.to.shared.u64 t, %1; cvt.u32.u64 %0, t; }" : "=r"(a) : "l"(p));
    return a;
}
__device__ __forceinline__ uint32_t sw128(uint32_t off) { return off ^ ((off >> 3) & 0x70); }

__device__ __forceinline__ uint32_t pack2h(float a, float b) {
    __half2 h = __floats2half2_rn(a, b);
    return *reinterpret_cast<uint32_t*>(&h);
}
__device__ __forceinline__ void ldsm_x4(uint32_t* r, uint32_t addr) {
    asm volatile("ldmatrix.sync.aligned.m8n8.x4.shared.b16 {%0,%1,%2,%3}, [%4];"
                 : "=r"(r[0]), "=r"(r[1]), "=r"(r[2]), "=r"(r[3]) : "r"(addr));
}
__device__ __forceinline__ void mma_f16(float* c, const uint32_t* a, uint32_t b0, uint32_t b1) {
    asm volatile("mma.sync.aligned.m16n8k16.row.col.f32.f16.f16.f32 "
                 "{%0,%1,%2,%3}, {%4,%5,%6,%7}, {%8,%9}, {%0,%1,%2,%3};"
                 : "+f"(c[0]), "+f"(c[1]), "+f"(c[2]), "+f"(c[3])
                 : "r"(a[0]), "r"(a[1]), "r"(a[2]), "r"(a[3]), "r"(b0), "r"(b1));
}
__device__ __forceinline__ void sts16(uint32_t addr, uint4 v) {
    asm volatile("st.shared.v4.b32 [%0], {%1,%2,%3,%4};"
                 :: "r"(addr), "r"(v.x), "r"(v.y), "r"(v.z), "r"(v.w) : "memory");
}
__device__ __forceinline__ void cp16(uint32_t dst, const void* src, uint32_t sz) {
    asm volatile("cp.async.cg.shared.global [%0], [%1], 16, %2;"
                 :: "r"(dst), "l"(src), "r"(sz) : "memory");
}
__device__ __forceinline__ void cp_commit_wait() {
    asm volatile("cp.async.commit_group;" ::: "memory");
    asm volatile("cp.async.wait_group 0;" ::: "memory");
}

// ---------------------------------------------------------------------------
// init: agg = (1+eps)*x  AND  xh = fp16(x)   (single read of x)
// ---------------------------------------------------------------------------
__global__ void init_kernel(const float* __restrict__ x,
                            const float* __restrict__ eps) {
    const float epsv = 1.0f + eps[0];
    size_t i = (size_t)blockIdx.x * blockDim.x + threadIdx.x;
    size_t n = (size_t)N_NODES * D_IN / 4;
    if (i < n) {
        float4 v = reinterpret_cast<const float4*>(x)[i];
        uint2 h;
        h.x = pack2h(v.x, v.y);
        h.y = pack2h(v.z, v.w);
        reinterpret_cast<uint2*>(g_xh)[i] = h;
        v.x *= epsv; v.y *= epsv; v.z *= epsv; v.w *= epsv;
        reinterpret_cast<float4*>(g_agg)[i] = v;
    }
}

// ---------------------------------------------------------------------------
// edge aggregation: gather fp16 rows, accumulate fp32, atomics on seg change
// ---------------------------------------------------------------------------
#define EDGES_PER_WARP 128

__global__ __launch_bounds__(256) void agg_kernel(
    const int*   __restrict__ edge_src,
    const int*   __restrict__ edge_dst,
    const float* __restrict__ edge_val)
{
    int gtid   = blockIdx.x * blockDim.x + threadIdx.x;
    int warpId = gtid >> 5;
    int lane   = threadIdx.x & 31;

    long start = (long)warpId * EDGES_PER_WARP;
    if (start >= N_EDGES) return;
    long end = start + EDGES_PER_WARP;
    if (end > N_EDGES) end = N_EDGES;

    float ax = 0.f, ay = 0.f, az = 0.f, aw = 0.f;
    int cur_dst = edge_dst[start];

    for (long e = start; e < end; ++e) {
        int d = edge_dst[e];
        if (d != cur_dst) {
            float* o = g_agg + (size_t)cur_dst * D_IN + lane * 4;
            atomicAdd(o + 0, ax); atomicAdd(o + 1, ay);
            atomicAdd(o + 2, az); atomicAdd(o + 3, aw);
            ax = ay = az = aw = 0.f;
            cur_dst = d;
        }
        int   s = edge_src[e];
        float v = edge_val[e];
        uint2 hv = *reinterpret_cast<const uint2*>(g_xh + (size_t)s * D_IN + lane * 4);
        float2 x01 = __half22float2(*reinterpret_cast<__half2*>(&hv.x));
        float2 x23 = __half22float2(*reinterpret_cast<__half2*>(&hv.y));
        ax += v * x01.x; ay += v * x01.y; az += v * x23.x; aw += v * x23.y;
    }
    float* o = g_agg + (size_t)cur_dst * D_IN + lane * 4;
    atomicAdd(o + 0, ax); atomicAdd(o + 1, ay);
    atomicAdd(o + 2, az); atomicAdd(o + 3, aw);
}

// ---------------------------------------------------------------------------
// weight transpose -> fp16
// ---------------------------------------------------------------------------
__global__ __launch_bounds__(256) void conv_b_kernel(const float* __restrict__ w1,
                                                     const float* __restrict__ w2)
{
    int idx = blockIdx.x * blockDim.x + threadIdx.x;
    if (idx < D_HID * D_IN) {
        int n = idx / D_IN, k = idx % D_IN;
        g_b1h[idx] = __float2half_rn(w1[(size_t)k * D_HID + n]);
    }
    int idx2 = idx - D_HID * D_IN;
    if (idx2 >= 0 && idx2 < D_OUT * D_HID) {
        int n = idx2 / D_HID, k = idx2 % D_HID;
        g_b2h[idx2] = __float2half_rn(w2[(size_t)k * D_OUT + n]);
    }
}

// ---------------------------------------------------------------------------
// mma.sync split-fp16 GEMM, BK=128 chunks, 2 CTAs/SM.
//   Block tile 128x128, 8 warps, warp tile 32x64.
//   SMEM per chunk: A_HI | A_LO | B, each 128 rows x 128 cols fp16 stored as
//   two 64-col SW128 sub-tiles (16 KB each) -> 96 KB total, single-buffered.
//   GEMM1 (K=128): exactly ONE sync in the whole mainloop.
//   AMODE 0: A = split(g_agg fp32) on the fly; AMODE 1: A hi/lo via cp.async.
// ---------------------------------------------------------------------------
template <int K, int NTOT, int AMODE, bool SPLIT>
__global__ __launch_bounds__(256, 2) void gemm_mma_kernel(
    const float* __restrict__ aggp,
    const __half* __restrict__ a_hi,
    const __half* __restrict__ a_lo,
    const __half* __restrict__ bmat,
    const float* __restrict__ bias,
    __half* __restrict__ o_hi,
    __half* __restrict__ o_lo,
    float* __restrict__ o_f32)
{
    constexpr int KCHUNKS = K / 128;
    constexpr uint32_t A_HI = 0, A_LO = 32768, B_OF = 65536;  // each 2 subs x 16KB

    extern __shared__ char smem[];
    const uint32_t sb = smem_u32(smem);

    const int tid   = threadIdx.x;
    const int lane  = tid & 31;
    const int wid   = tid >> 5;
    const int wm0   = (wid & 3) * 32;
    const int wn0   = (wid >> 2) * 64;
    const int row0  = blockIdx.x * 128;
    const int ncol0 = blockIdx.y * 128;

    float acc[2][8][4];
    #pragma unroll
    for (int i = 0; i < 2; ++i)
        #pragma unroll
        for (int j = 0; j < 8; ++j)
            #pragma unroll
            for (int q = 0; q < 4; ++q) acc[i][j][q] = 0.f;

    for (int kc = 0; kc < KCHUNKS; ++kc) {
        // -------- stage B (cp.async): 2048 16B units --------
        #pragma unroll
        for (int u = tid; u < 2048; u += 256) {
            int r = u >> 4, g = u & 15;          // g: 16B group within 128 cols
            int sub = g >> 3, gi = g & 7;
            const __half* src = bmat + (size_t)(ncol0 + r) * K + kc * 128 + g * 8;
            cp16(sb + B_OF + sub * 16384 + sw128((uint32_t)(r * 128 + gi * 16)),
                 src, 16u);
        }
        // -------- stage A --------
        if (AMODE == 0) {
            #pragma unroll
            for (int u = tid; u < 2048; u += 256) {
                int r = u >> 4, g = u & 15;
                int sub = g >> 3, gi = g & 7;
                int row = row0 + r;
                uint4 hi = make_uint4(0, 0, 0, 0), lo = make_uint4(0, 0, 0, 0);
                if (row < N_NODES) {
                    const float* pa = aggp + (size_t)row * K + kc * 128 + g * 8;
                    float4 a0 = *reinterpret_cast<const float4*>(pa);
                    float4 a1 = *reinterpret_cast<const float4*>(pa + 4);
                    float v[8] = {a0.x, a0.y, a0.z, a0.w, a1.x, a1.y, a1.z, a1.w};
                    float h[8], l[8];
                    #pragma unroll
                    for (int j = 0; j < 8; ++j) {
                        h[j] = __half2float(__float2half_rn(v[j]));
                        l[j] = v[j] - h[j];
                    }
                    hi = make_uint4(pack2h(h[0], h[1]), pack2h(h[2], h[3]),
                                    pack2h(h[4], h[5]), pack2h(h[6], h[7]));
                    lo = make_uint4(pack2h(l[0], l[1]), pack2h(l[2], l[3]),
                                    pack2h(l[4], l[5]), pack2h(l[6], l[7]));
                }
                uint32_t off = sub * 16384 + sw128((uint32_t)(r * 128 + gi * 16));
                sts16(sb + A_HI + off, hi);
                sts16(sb + A_LO + off, lo);
            }
        } else {
            #pragma unroll
            for (int u = tid; u < 4096; u += 256) {
                int buf = u >> 11, rem = u & 2047;
                int r = rem >> 4, g = rem & 15;
                int sub = g >> 3, gi = g & 7;
                int row = row0 + r;
                const __half* src = (buf ? a_lo : a_hi) +
                    (size_t)row * K + kc * 128 + g * 8;
                uint32_t off = sub * 16384 + sw128((uint32_t)(r * 128 + gi * 16));
                cp16(sb + (buf ? A_LO : A_HI) + off, src, row < N_NODES ? 16u : 0u);
            }
        }
        cp_commit_wait();
        __syncthreads();

        // -------- MMA: 8 k16 steps --------
        #pragma unroll
        for (int ks = 0; ks < 8; ++ks) {
            const uint32_t ksub = (uint32_t)(ks >> 2) * 16384;
            const int kb = (ks & 3) * 32;        // byte offset within sub row
            uint32_t ah[2][4], al[2][4];
            #pragma unroll
            for (int mi = 0; mi < 2; ++mi) {
                uint32_t off = ksub + sw128((uint32_t)((wm0 + mi * 16 + (lane & 15)) * 128 +
                                                       kb + (lane >> 4) * 16));
                ldsm_x4(ah[mi], sb + A_HI + off);
                ldsm_x4(al[mi], sb + A_LO + off);
            }
            #pragma unroll
            for (int pi = 0; pi < 4; ++pi) {
                const int q = lane >> 3;
                uint32_t off = ksub + sw128((uint32_t)(
                    (wn0 + pi * 16 + ((q >> 1) << 3) + (lane & 7)) * 128 +
                    kb + (q & 1) * 16));
                uint32_t bh[4];
                ldsm_x4(bh, sb + B_OF + off);
                #pragma unroll
                for (int mi = 0; mi < 2; ++mi) {
                    #pragma unroll
                    for (int hh = 0; hh < 2; ++hh) {
                        float* c = acc[mi][pi * 2 + hh];
                        mma_f16(c, ah[mi], bh[2 * hh], bh[2 * hh + 1]);
                        mma_f16(c, al[mi], bh[2 * hh], bh[2 * hh + 1]);
                    }
                }
            }
        }
        if (kc + 1 < KCHUNKS) __syncthreads();
    }

    // -------- epilogue --------
    #pragma unroll
    for (int mi = 0; mi < 2; ++mi) {
        #pragma unroll
        for (int ni = 0; ni < 8; ++ni) {
            int col = ncol0 + wn0 + ni * 8 + (lane & 3) * 2;
            int rbase = row0 + wm0 + mi * 16 + (lane >> 2);
            float2 bb = *reinterpret_cast<const float2*>(bias + col);
            #pragma unroll
            for (int p = 0; p < 2; ++p) {
                int row = rbase + p * 8;
                if (row >= N_NODES) continue;
                float v0 = acc[mi][ni][2 * p]     + bb.x;
                float v1 = acc[mi][ni][2 * p + 1] + bb.y;
                if (SPLIT) {
                    v0 = fmaxf(v0, 0.f); v1 = fmaxf(v1, 0.f);
                    float h0 = __half2float(__float2half_rn(v0));
                    float h1 = __half2float(__float2half_rn(v1));
                    *reinterpret_cast<uint32_t*>(o_hi + (size_t)row * NTOT + col) =
                        pack2h(h0, h1);
                    *reinterpret_cast<uint32_t*>(o_lo + (size_t)row * NTOT + col) =
                        pack2h(v0 - h0, v1 - h1);
                } else {
                    *reinterpret_cast<float2*>(o_f32 + (size_t)row * NTOT + col) =
                        make_float2(v0, v1);
                }
            }
        }
    }
}

// ---------------------------------------------------------------------------
// Launch. Inputs: x, edge_src, edge_dst, edge_val, eps, w1, b1, w2, b2
// ---------------------------------------------------------------------------
extern "C" void kernel_launch(void* const* d_in, const int* in_sizes, int n_in,
                              void* d_out, int out_size)
{
    const float* x        = (const float*)d_in[0];
    const int*   edge_src = (const int*)  d_in[1];
    const int*   edge_dst = (const int*)  d_in[2];
    const float* edge_val = (const float*)d_in[3];
    const float* eps      = (const float*)d_in[4];
    const float* w1       = (const float*)d_in[5];
    const float* b1       = (const float*)d_in[6];
    const float* w2       = (const float*)d_in[7];
    const float* b2       = (const float*)d_in[8];
    float* out = (float*)d_out;

    float* aggp;
    __half *hid_hi, *hid_lo, *b1h, *b2h;
    cudaGetSymbolAddress((void**)&aggp,   g_agg);
    cudaGetSymbolAddress((void**)&hid_hi, g_hid_hi);
    cudaGetSymbolAddress((void**)&hid_lo, g_hid_lo);
    cudaGetSymbolAddress((void**)&b1h, g_b1h);
    cudaGetSymbolAddress((void**)&b2h, g_b2h);

    // init: agg = (1+eps)x, xh = fp16(x)
    {
        size_t n = (size_t)N_NODES * D_IN / 4;
        init_kernel<<<(int)((n + 255) / 256), 256>>>(x, eps);
    }
    // aggregation (fp16 gather)
    {
        int warps = (N_EDGES + EDGES_PER_WARP - 1) / EDGES_PER_WARP;
        agg_kernel<<<(warps * 32 + 255) / 256, 256>>>(edge_src, edge_dst, edge_val);
    }
    // weight transpose -> fp16
    conv_b_kernel<<<(D_HID * D_IN + D_OUT * D_HID + 255) / 256, 256>>>(w1, w2);

    const int grid_m = (N_NODES + 127) / 128;
    constexpr int SMEM = 98304;   // 3 x 32 KB

    // GEMM1: A = split(agg); [N,128] x [128,256] -> hid split fp16
    {
        auto kfn = gemm_mma_kernel<D_IN, D_HID, 0, true>;
        cudaFuncSetAttribute(kfn, cudaFuncAttributeMaxDynamicSharedMemorySize, SMEM);
        kfn<<<dim3(grid_m, D_HID / 128), 256, SMEM>>>(
            aggp, nullptr, nullptr, b1h, b1, hid_hi, hid_lo, nullptr);
    }
    // GEMM2: [N,256] x [256,128] -> out fp32
    {
        auto kfn = gemm_mma_kernel<D_HID, D_OUT, 1, false>;
        cudaFuncSetAttribute(kfn, cudaFuncAttributeMaxDynamicSharedMemorySize, SMEM);
        kfn<<<dim3(grid_m, 1), 256, SMEM>>>(
            nullptr, hid_hi, hid_lo, b2h, b2, nullptr, nullptr, out);
    }
}

// round 7
// speedup vs baseline: 1.0734x; 1.0734x over previous
#include <cuda_runtime.h>
#include <cuda_fp16.h>
#include <cstdint>

#define N_NODES 50000
#define N_EDGES 800000
#define D_IN    128
#define D_HID   256
#define D_OUT   128

// ---------------------------------------------------------------------------
// Device scratch (no cudaMalloc allowed)
// ---------------------------------------------------------------------------
__device__ float  g_agg   [(size_t)N_NODES * D_IN];
__device__ __half g_xh    [(size_t)N_NODES * D_IN];    // fp16 copy of x (gather)
__device__ __half g_hid_hi[(size_t)N_NODES * D_HID];
__device__ __half g_hid_lo[(size_t)N_NODES * D_HID];
__device__ __half g_b1h   [D_HID * D_IN];              // w1^T fp16 [256,128]
__device__ __half g_b2h   [D_OUT * D_HID];             // w2^T fp16 [128,256]

// ---------------------------------------------------------------------------
// helpers
// ---------------------------------------------------------------------------
__device__ __forceinline__ uint32_t smem_u32(const void* p) {
    uint32_t a;
    asm("{ .reg .u64 t; cvta.to.shared.u64 t, %1; cvt.u32.u64 %0, t; }" : "=r"(a) : "l"(p));
    return a;
}
__device__ __forceinline__ uint32_t sw128(uint32_t off) { return off ^ ((off >> 3) & 0x70); }

__device__ __forceinline__ uint32_t pack2h(float a, float b) {
    __half2 h = __floats2half2_rn(a, b);
    return *reinterpret_cast<uint32_t*>(&h);
}
__device__ __forceinline__ void ldsm_x4(uint32_t* r, uint32_t addr) {
    asm volatile("ldmatrix.sync.aligned.m8n8.x4.shared.b16 {%0,%1,%2,%3}, [%4];"
                 : "=r"(r[0]), "=r"(r[1]), "=r"(r[2]), "=r"(r[3]) : "r"(addr));
}
__device__ __forceinline__ void mma_f16(float* c, const uint32_t* a, uint32_t b0, uint32_t b1) {
    asm volatile("mma.sync.aligned.m16n8k16.row.col.f32.f16.f16.f32 "
                 "{%0,%1,%2,%3}, {%4,%5,%6,%7}, {%8,%9}, {%0,%1,%2,%3};"
                 : "+f"(c[0]), "+f"(c[1]), "+f"(c[2]), "+f"(c[3])
                 : "r"(a[0]), "r"(a[1]), "r"(a[2]), "r"(a[3]), "r"(b0), "r"(b1));
}
__device__ __forceinline__ void sts16(uint32_t addr, uint4 v) {
    asm volatile("st.shared.v4.b32 [%0], {%1,%2,%3,%4};"
                 :: "r"(addr), "r"(v.x), "r"(v.y), "r"(v.z), "r"(v.w) : "memory");
}
__device__ __forceinline__ void cp16(uint32_t dst, const void* src, uint32_t sz) {
    asm volatile("cp.async.cg.shared.global [%0], [%1], 16, %2;"
                 :: "r"(dst), "l"(src), "r"(sz) : "memory");
}
__device__ __forceinline__ void cp_commit_wait() {
    asm volatile("cp.async.commit_group;" ::: "memory");
    asm volatile("cp.async.wait_group 0;" ::: "memory");
}

// ---------------------------------------------------------------------------
// init: agg = (1+eps)*x  AND  xh = fp16(x)
// ---------------------------------------------------------------------------
__global__ void init_kernel(const float* __restrict__ x,
                            const float* __restrict__ eps) {
    const float epsv = 1.0f + eps[0];
    size_t i = (size_t)blockIdx.x * blockDim.x + threadIdx.x;
    size_t n = (size_t)N_NODES * D_IN / 4;
    if (i < n) {
        float4 v = reinterpret_cast<const float4*>(x)[i];
        uint2 h;
        h.x = pack2h(v.x, v.y);
        h.y = pack2h(v.z, v.w);
        reinterpret_cast<uint2*>(g_xh)[i] = h;
        v.x *= epsv; v.y *= epsv; v.z *= epsv; v.w *= epsv;
        reinterpret_cast<float4*>(g_agg)[i] = v;
    }
}

// ---------------------------------------------------------------------------
// edge aggregation: gather fp16 rows, accumulate fp32, atomics on seg change
// ---------------------------------------------------------------------------
#define EDGES_PER_WARP 128

__global__ __launch_bounds__(256) void agg_kernel(
    const int*   __restrict__ edge_src,
    const int*   __restrict__ edge_dst,
    const float* __restrict__ edge_val)
{
    int gtid   = blockIdx.x * blockDim.x + threadIdx.x;
    int warpId = gtid >> 5;
    int lane   = threadIdx.x & 31;

    long start = (long)warpId * EDGES_PER_WARP;
    if (start >= N_EDGES) return;
    long end = start + EDGES_PER_WARP;
    if (end > N_EDGES) end = N_EDGES;

    float ax = 0.f, ay = 0.f, az = 0.f, aw = 0.f;
    int cur_dst = edge_dst[start];

    for (long e = start; e < end; ++e) {
        int d = edge_dst[e];
        if (d != cur_dst) {
            float* o = g_agg + (size_t)cur_dst * D_IN + lane * 4;
            atomicAdd(o + 0, ax); atomicAdd(o + 1, ay);
            atomicAdd(o + 2, az); atomicAdd(o + 3, aw);
            ax = ay = az = aw = 0.f;
            cur_dst = d;
        }
        int   s = edge_src[e];
        float v = edge_val[e];
        uint2 hv = *reinterpret_cast<const uint2*>(g_xh + (size_t)s * D_IN + lane * 4);
        float2 x01 = __half22float2(*reinterpret_cast<__half2*>(&hv.x));
        float2 x23 = __half22float2(*reinterpret_cast<__half2*>(&hv.y));
        ax += v * x01.x; ay += v * x01.y; az += v * x23.x; aw += v * x23.y;
    }
    float* o = g_agg + (size_t)cur_dst * D_IN + lane * 4;
    atomicAdd(o + 0, ax); atomicAdd(o + 1, ay);
    atomicAdd(o + 2, az); atomicAdd(o + 3, aw);
}

// ---------------------------------------------------------------------------
// weight transpose -> fp16
// ---------------------------------------------------------------------------
__global__ __launch_bounds__(256) void conv_b_kernel(const float* __restrict__ w1,
                                                     const float* __restrict__ w2)
{
    int idx = blockIdx.x * blockDim.x + threadIdx.x;
    if (idx < D_HID * D_IN) {
        int n = idx / D_IN, k = idx % D_IN;
        g_b1h[idx] = __float2half_rn(w1[(size_t)k * D_HID + n]);
    }
    int idx2 = idx - D_HID * D_IN;
    if (idx2 >= 0 && idx2 < D_OUT * D_HID) {
        int n = idx2 / D_HID, k = idx2 % D_HID;
        g_b2h[idx2] = __float2half_rn(w2[(size_t)k * D_OUT + n]);
    }
}

// ---------------------------------------------------------------------------
// mma.sync split-fp16 GEMM, block tile 64x128, warp tile 32x32, 3 CTAs/SM.
//   8 warps in 2 (row) x 4 (col). BK=128 per chunk.
//   SMEM: A_HI (16KB) | A_LO (16KB) | B (32KB) = 64 KB; rows stored as
//   two 64-col SW128 sub-tiles (A sub stride 8KB, B sub stride 16KB).
//   AMODE 0: A = split(g_agg fp32) on the fly; AMODE 1: A hi/lo via cp.async.
// ---------------------------------------------------------------------------
template <int K, int NTOT, int AMODE, bool SPLIT>
__global__ __launch_bounds__(256, 3) void gemm_mma_kernel(
    const float* __restrict__ aggp,
    const __half* __restrict__ a_hi,
    const __half* __restrict__ a_lo,
    const __half* __restrict__ bmat,
    const float* __restrict__ bias,
    __half* __restrict__ o_hi,
    __half* __restrict__ o_lo,
    float* __restrict__ o_f32)
{
    constexpr int KCHUNKS = K / 128;
    constexpr uint32_t A_HI = 0, A_LO = 16384, B_OF = 32768;

    extern __shared__ char smem[];
    const uint32_t sb = smem_u32(smem);

    const int tid   = threadIdx.x;
    const int lane  = tid & 31;
    const int wid   = tid >> 5;
    const int wm0   = (wid >> 2) * 32;   // 2 warp-rows
    const int wn0   = (wid & 3) * 32;    // 4 warp-cols
    const int row0  = blockIdx.x * 64;
    const int ncol0 = blockIdx.y * 128;

    float acc[2][4][4];
    #pragma unroll
    for (int i = 0; i < 2; ++i)
        #pragma unroll
        for (int j = 0; j < 4; ++j)
            #pragma unroll
            for (int q = 0; q < 4; ++q) acc[i][j][q] = 0.f;

    for (int kc = 0; kc < KCHUNKS; ++kc) {
        // -------- stage B (cp.async): 2048 16B units --------
        #pragma unroll
        for (int u = tid; u < 2048; u += 256) {
            int r = u >> 4, g = u & 15;
            int sub = g >> 3, gi = g & 7;
            const __half* src = bmat + (size_t)(ncol0 + r) * K + kc * 128 + g * 8;
            cp16(sb + B_OF + sub * 16384 + sw128((uint32_t)(r * 128 + gi * 16)),
                 src, 16u);
        }
        // -------- stage A: 1024 units (64 rows x 16 groups) --------
        if (AMODE == 0) {
            #pragma unroll
            for (int u = tid; u < 1024; u += 256) {
                int r = u >> 4, g = u & 15;
                int sub = g >> 3, gi = g & 7;
                int row = row0 + r;
                uint4 hi = make_uint4(0, 0, 0, 0), lo = make_uint4(0, 0, 0, 0);
                if (row < N_NODES) {
                    const float* pa = aggp + (size_t)row * K + kc * 128 + g * 8;
                    float4 a0 = *reinterpret_cast<const float4*>(pa);
                    float4 a1 = *reinterpret_cast<const float4*>(pa + 4);
                    float v[8] = {a0.x, a0.y, a0.z, a0.w, a1.x, a1.y, a1.z, a1.w};
                    float h[8], l[8];
                    #pragma unroll
                    for (int j = 0; j < 8; ++j) {
                        h[j] = __half2float(__float2half_rn(v[j]));
                        l[j] = v[j] - h[j];
                    }
                    hi = make_uint4(pack2h(h[0], h[1]), pack2h(h[2], h[3]),
                                    pack2h(h[4], h[5]), pack2h(h[6], h[7]));
                    lo = make_uint4(pack2h(l[0], l[1]), pack2h(l[2], l[3]),
                                    pack2h(l[4], l[5]), pack2h(l[6], l[7]));
                }
                uint32_t off = sub * 8192 + sw128((uint32_t)(r * 128 + gi * 16));
                sts16(sb + A_HI + off, hi);
                sts16(sb + A_LO + off, lo);
            }
        } else {
            #pragma unroll
            for (int u = tid; u < 2048; u += 256) {
                int buf = u >> 10, rem = u & 1023;
                int r = rem >> 4, g = rem & 15;
                int sub = g >> 3, gi = g & 7;
                int row = row0 + r;
                const __half* src = (buf ? a_lo : a_hi) +
                    (size_t)row * K + kc * 128 + g * 8;
                uint32_t off = sub * 8192 + sw128((uint32_t)(r * 128 + gi * 16));
                cp16(sb + (buf ? A_LO : A_HI) + off, src, row < N_NODES ? 16u : 0u);
            }
        }
        cp_commit_wait();
        __syncthreads();

        // -------- MMA: 8 k16 steps --------
        #pragma unroll
        for (int ks = 0; ks < 8; ++ks) {
            const uint32_t ksubA = (uint32_t)(ks >> 2) * 8192;
            const uint32_t ksubB = (uint32_t)(ks >> 2) * 16384;
            const int kb = (ks & 3) * 32;
            uint32_t ah[2][4], al[2][4];
            #pragma unroll
            for (int mi = 0; mi < 2; ++mi) {
                uint32_t off = ksubA + sw128((uint32_t)((wm0 + mi * 16 + (lane & 15)) * 128 +
                                                        kb + (lane >> 4) * 16));
                ldsm_x4(ah[mi], sb + A_HI + off);
                ldsm_x4(al[mi], sb + A_LO + off);
            }
            uint32_t bh[2][4];
            #pragma unroll
            for (int pi = 0; pi < 2; ++pi) {
                const int q = lane >> 3;
                uint32_t off = ksubB + sw128((uint32_t)(
                    (wn0 + pi * 16 + ((q >> 1) << 3) + (lane & 7)) * 128 +
                    kb + (q & 1) * 16));
                ldsm_x4(bh[pi], sb + B_OF + off);
            }
            #pragma unroll
            for (int mi = 0; mi < 2; ++mi) {
                #pragma unroll
                for (int pi = 0; pi < 2; ++pi) {
                    #pragma unroll
                    for (int hh = 0; hh < 2; ++hh) {
                        float* c = acc[mi][pi * 2 + hh];
                        mma_f16(c, ah[mi], bh[pi][2 * hh], bh[pi][2 * hh + 1]);
                        mma_f16(c, al[mi], bh[pi][2 * hh], bh[pi][2 * hh + 1]);
                    }
                }
            }
        }
        if (kc + 1 < KCHUNKS) __syncthreads();
    }

    // -------- epilogue --------
    #pragma unroll
    for (int mi = 0; mi < 2; ++mi) {
        #pragma unroll
        for (int ni = 0; ni < 4; ++ni) {
            int col = ncol0 + wn0 + ni * 8 + (lane & 3) * 2;
            int rbase = row0 + wm0 + mi * 16 + (lane >> 2);
            float2 bb = *reinterpret_cast<const float2*>(bias + col);
            #pragma unroll
            for (int p = 0; p < 2; ++p) {
                int row = rbase + p * 8;
                if (row >= N_NODES) continue;
                float v0 = acc[mi][ni][2 * p]     + bb.x;
                float v1 = acc[mi][ni][2 * p + 1] + bb.y;
                if (SPLIT) {
                    v0 = fmaxf(v0, 0.f); v1 = fmaxf(v1, 0.f);
                    float h0 = __half2float(__float2half_rn(v0));
                    float h1 = __half2float(__float2half_rn(v1));
                    *reinterpret_cast<uint32_t*>(o_hi + (size_t)row * NTOT + col) =
                        pack2h(h0, h1);
                    *reinterpret_cast<uint32_t*>(o_lo + (size_t)row * NTOT + col) =
                        pack2h(v0 - h0, v1 - h1);
                } else {
                    *reinterpret_cast<float2*>(o_f32 + (size_t)row * NTOT + col) =
                        make_float2(v0, v1);
                }
            }
        }
    }
}

// ---------------------------------------------------------------------------
// Launch. Inputs: x, edge_src, edge_dst, edge_val, eps, w1, b1, w2, b2
// ---------------------------------------------------------------------------
extern "C" void kernel_launch(void* const* d_in, const int* in_sizes, int n_in,
                              void* d_out, int out_size)
{
    const float* x        = (const float*)d_in[0];
    const int*   edge_src = (const int*)  d_in[1];
    const int*   edge_dst = (const int*)  d_in[2];
    const float* edge_val = (const float*)d_in[3];
    const float* eps      = (const float*)d_in[4];
    const float* w1       = (const float*)d_in[5];
    const float* b1       = (const float*)d_in[6];
    const float* w2       = (const float*)d_in[7];
    const float* b2       = (const float*)d_in[8];
    float* out = (float*)d_out;

    float* aggp;
    __half *hid_hi, *hid_lo, *b1h, *b2h;
    cudaGetSymbolAddress((void**)&aggp,   g_agg);
    cudaGetSymbolAddress((void**)&hid_hi, g_hid_hi);
    cudaGetSymbolAddress((void**)&hid_lo, g_hid_lo);
    cudaGetSymbolAddress((void**)&b1h, g_b1h);
    cudaGetSymbolAddress((void**)&b2h, g_b2h);

    // init: agg = (1+eps)x, xh = fp16(x)
    {
        size_t n = (size_t)N_NODES * D_IN / 4;
        init_kernel<<<(int)((n + 255) / 256), 256>>>(x, eps);
    }
    // aggregation (fp16 gather)
    {
        int warps = (N_EDGES + EDGES_PER_WARP - 1) / EDGES_PER_WARP;
        agg_kernel<<<(warps * 32 + 255) / 256, 256>>>(edge_src, edge_dst, edge_val);
    }
    // weight transpose -> fp16
    conv_b_kernel<<<(D_HID * D_IN + D_OUT * D_HID + 255) / 256, 256>>>(w1, w2);

    const int grid_m = (N_NODES + 63) / 64;
    constexpr int SMEM = 65536;   // 16 + 16 + 32 KB

    // GEMM1: A = split(agg); [N,128] x [128,256] -> hid split fp16
    {
        auto kfn = gemm_mma_kernel<D_IN, D_HID, 0, true>;
        cudaFuncSetAttribute(kfn, cudaFuncAttributeMaxDynamicSharedMemorySize, SMEM);
        kfn<<<dim3(grid_m, D_HID / 128), 256, SMEM>>>(
            aggp, nullptr, nullptr, b1h, b1, hid_hi, hid_lo, nullptr);
    }
    // GEMM2: [N,256] x [256,128] -> out fp32
    {
        auto kfn = gemm_mma_kernel<D_HID, D_OUT, 1, false>;
        cudaFuncSetAttribute(kfn, cudaFuncAttributeMaxDynamicSharedMemorySize, SMEM);
        kfn<<<dim3(grid_m, 1), 256, SMEM>>>(
            nullptr, hid_hi, hid_lo, b2h, b2, nullptr, nullptr, out);
    }
}

// round 8
// speedup vs baseline: 1.0835x; 1.0094x over previous
#include <cuda_runtime.h>
#include <cuda_fp16.h>
#include <cstdint>

#define N_NODES 50000
#define N_EDGES 800000
#define D_IN    128
#define D_HID   256
#define D_OUT   128

// ---------------------------------------------------------------------------
// Device scratch (no cudaMalloc allowed)
// ---------------------------------------------------------------------------
__device__ float  g_agg   [(size_t)N_NODES * D_IN];
__device__ __half g_xh    [(size_t)N_NODES * D_IN];    // fp16 copy of x (gather)
__device__ __half g_hid_hi[(size_t)N_NODES * D_HID];
__device__ __half g_hid_lo[(size_t)N_NODES * D_HID];
__device__ __half g_b1h   [D_HID * D_IN];              // w1^T fp16 [256,128]
__device__ __half g_b2h   [D_OUT * D_HID];             // w2^T fp16 [128,256]

// ---------------------------------------------------------------------------
// helpers
// ---------------------------------------------------------------------------
__device__ __forceinline__ uint32_t smem_u32(const void* p) {
    uint32_t a;
    asm("{ .reg .u64 t; cvta.to.shared.u64 t, %1; cvt.u32.u64 %0, t; }" : "=r"(a) : "l"(p));
    return a;
}
__device__ __forceinline__ uint32_t sw128(uint32_t off) { return off ^ ((off >> 3) & 0x70); }

__device__ __forceinline__ uint32_t pack2h(float a, float b) {
    __half2 h = __floats2half2_rn(a, b);
    return *reinterpret_cast<uint32_t*>(&h);
}
__device__ __forceinline__ void ldsm_x4(uint32_t* r, uint32_t addr) {
    asm volatile("ldmatrix.sync.aligned.m8n8.x4.shared.b16 {%0,%1,%2,%3}, [%4];"
                 : "=r"(r[0]), "=r"(r[1]), "=r"(r[2]), "=r"(r[3]) : "r"(addr));
}
__device__ __forceinline__ void mma_f16(float* c, const uint32_t* a, uint32_t b0, uint32_t b1) {
    asm volatile("mma.sync.aligned.m16n8k16.row.col.f32.f16.f16.f32 "
                 "{%0,%1,%2,%3}, {%4,%5,%6,%7}, {%8,%9}, {%0,%1,%2,%3};"
                 : "+f"(c[0]), "+f"(c[1]), "+f"(c[2]), "+f"(c[3])
                 : "r"(a[0]), "r"(a[1]), "r"(a[2]), "r"(a[3]), "r"(b0), "r"(b1));
}
__device__ __forceinline__ void sts16(uint32_t addr, uint4 v) {
    asm volatile("st.shared.v4.b32 [%0], {%1,%2,%3,%4};"
                 :: "r"(addr), "r"(v.x), "r"(v.y), "r"(v.z), "r"(v.w) : "memory");
}
__device__ __forceinline__ void cp16(uint32_t dst, const void* src, uint32_t sz) {
    asm volatile("cp.async.cg.shared.global [%0], [%1], 16, %2;"
                 :: "r"(dst), "l"(src), "r"(sz) : "memory");
}
__device__ __forceinline__ void cp_commit_wait() {
    asm volatile("cp.async.commit_group;" ::: "memory");
    asm volatile("cp.async.wait_group 0;" ::: "memory");
}

// ---------------------------------------------------------------------------
// init: agg = (1+eps)*x  AND  xh = fp16(x)
// ---------------------------------------------------------------------------
__global__ void init_kernel(const float* __restrict__ x,
                            const float* __restrict__ eps) {
    const float epsv = 1.0f + eps[0];
    size_t i = (size_t)blockIdx.x * blockDim.x + threadIdx.x;
    size_t n = (size_t)N_NODES * D_IN / 4;
    if (i < n) {
        float4 v = reinterpret_cast<const float4*>(x)[i];
        uint2 h;
        h.x = pack2h(v.x, v.y);
        h.y = pack2h(v.z, v.w);
        reinterpret_cast<uint2*>(g_xh)[i] = h;
        v.x *= epsv; v.y *= epsv; v.z *= epsv; v.w *= epsv;
        reinterpret_cast<float4*>(g_agg)[i] = v;
    }
}

// ---------------------------------------------------------------------------
// edge aggregation: gather fp16 rows, accumulate fp32, atomics on seg change
// ---------------------------------------------------------------------------
#define EDGES_PER_WARP 128

__global__ __launch_bounds__(256) void agg_kernel(
    const int*   __restrict__ edge_src,
    const int*   __restrict__ edge_dst,
    const float* __restrict__ edge_val)
{
    int gtid   = blockIdx.x * blockDim.x + threadIdx.x;
    int warpId = gtid >> 5;
    int lane   = threadIdx.x & 31;

    long start = (long)warpId * EDGES_PER_WARP;
    if (start >= N_EDGES) return;
    long end = start + EDGES_PER_WARP;
    if (end > N_EDGES) end = N_EDGES;

    float ax = 0.f, ay = 0.f, az = 0.f, aw = 0.f;
    int cur_dst = edge_dst[start];

    for (long e = start; e < end; ++e) {
        int d = edge_dst[e];
        if (d != cur_dst) {
            float* o = g_agg + (size_t)cur_dst * D_IN + lane * 4;
            atomicAdd(o + 0, ax); atomicAdd(o + 1, ay);
            atomicAdd(o + 2, az); atomicAdd(o + 3, aw);
            ax = ay = az = aw = 0.f;
            cur_dst = d;
        }
        int   s = edge_src[e];
        float v = edge_val[e];
        uint2 hv = *reinterpret_cast<const uint2*>(g_xh + (size_t)s * D_IN + lane * 4);
        float2 x01 = __half22float2(*reinterpret_cast<__half2*>(&hv.x));
        float2 x23 = __half22float2(*reinterpret_cast<__half2*>(&hv.y));
        ax += v * x01.x; ay += v * x01.y; az += v * x23.x; aw += v * x23.y;
    }
    float* o = g_agg + (size_t)cur_dst * D_IN + lane * 4;
    atomicAdd(o + 0, ax); atomicAdd(o + 1, ay);
    atomicAdd(o + 2, az); atomicAdd(o + 3, aw);
}

// ---------------------------------------------------------------------------
// weight transpose -> fp16
// ---------------------------------------------------------------------------
__global__ __launch_bounds__(256) void conv_b_kernel(const float* __restrict__ w1,
                                                     const float* __restrict__ w2)
{
    int idx = blockIdx.x * blockDim.x + threadIdx.x;
    if (idx < D_HID * D_IN) {
        int n = idx / D_IN, k = idx % D_IN;
        g_b1h[idx] = __float2half_rn(w1[(size_t)k * D_HID + n]);
    }
    int idx2 = idx - D_HID * D_IN;
    if (idx2 >= 0 && idx2 < D_OUT * D_HID) {
        int n = idx2 / D_HID, k = idx2 % D_HID;
        g_b2h[idx2] = __float2half_rn(w2[(size_t)k * D_OUT + n]);
    }
}

// ---------------------------------------------------------------------------
// GEMM1: 64 rows x 256 cols per CTA, A staged ONCE (split on the fly from
// g_agg fp32), two sequential N-tiles with B re-staged; epilogue of tile0
// overlaps cp.async of B(tile1). 8 warps (2x4), warp tile 32x32, 3 CTAs/SM.
// SMEM: A_HI 16KB | A_LO 16KB | B 32KB.
// ---------------------------------------------------------------------------
__global__ __launch_bounds__(256, 3) void gemm1_kernel(
    const float* __restrict__ aggp,
    const __half* __restrict__ bmat,   // [256,128] K-major
    const float* __restrict__ bias,
    __half* __restrict__ o_hi,
    __half* __restrict__ o_lo)
{
    constexpr int K = D_IN;
    constexpr uint32_t A_HI = 0, A_LO = 16384, B_OF = 32768;

    extern __shared__ char smem[];
    const uint32_t sb = smem_u32(smem);

    const int tid  = threadIdx.x;
    const int lane = tid & 31;
    const int wid  = tid >> 5;
    const int wm0  = (wid >> 2) * 32;
    const int wn0  = (wid & 3) * 32;
    const int row0 = blockIdx.x * 64;

    // ---- stage B tile0 (cp.async) ----
    #pragma unroll
    for (int u = tid; u < 2048; u += 256) {
        int r = u >> 4, g = u & 15;
        int sub = g >> 3, gi = g & 7;
        const __half* src = bmat + (size_t)r * K + g * 8;
        cp16(sb + B_OF + sub * 16384 + sw128((uint32_t)(r * 128 + gi * 16)), src, 16u);
    }
    // ---- stage A (split fp32 -> hi/lo fp16), once ----
    #pragma unroll
    for (int u = tid; u < 1024; u += 256) {
        int r = u >> 4, g = u & 15;
        int sub = g >> 3, gi = g & 7;
        int row = row0 + r;
        uint4 hi = make_uint4(0, 0, 0, 0), lo = make_uint4(0, 0, 0, 0);
        if (row < N_NODES) {
            const float* pa = aggp + (size_t)row * K + g * 8;
            float4 a0 = *reinterpret_cast<const float4*>(pa);
            float4 a1 = *reinterpret_cast<const float4*>(pa + 4);
            float v[8] = {a0.x, a0.y, a0.z, a0.w, a1.x, a1.y, a1.z, a1.w};
            float h[8], l[8];
            #pragma unroll
            for (int j = 0; j < 8; ++j) {
                h[j] = __half2float(__float2half_rn(v[j]));
                l[j] = v[j] - h[j];
            }
            hi = make_uint4(pack2h(h[0], h[1]), pack2h(h[2], h[3]),
                            pack2h(h[4], h[5]), pack2h(h[6], h[7]));
            lo = make_uint4(pack2h(l[0], l[1]), pack2h(l[2], l[3]),
                            pack2h(l[4], l[5]), pack2h(l[6], l[7]));
        }
        uint32_t off = sub * 8192 + sw128((uint32_t)(r * 128 + gi * 16));
        sts16(sb + A_HI + off, hi);
        sts16(sb + A_LO + off, lo);
    }
    cp_commit_wait();
    __syncthreads();

    // A fragments are reused across both tiles: preload per-ks inside loops.
    for (int t = 0; t < 2; ++t) {
        float acc[2][4][4];
        #pragma unroll
        for (int i = 0; i < 2; ++i)
            #pragma unroll
            for (int j = 0; j < 4; ++j)
                #pragma unroll
                for (int q = 0; q < 4; ++q) acc[i][j][q] = 0.f;

        // ---- MMA burst: 8 k16 steps ----
        #pragma unroll
        for (int ks = 0; ks < 8; ++ks) {
            const uint32_t ksubA = (uint32_t)(ks >> 2) * 8192;
            const uint32_t ksubB = (uint32_t)(ks >> 2) * 16384;
            const int kb = (ks & 3) * 32;
            uint32_t ah[2][4], al[2][4];
            #pragma unroll
            for (int mi = 0; mi < 2; ++mi) {
                uint32_t off = ksubA + sw128((uint32_t)((wm0 + mi * 16 + (lane & 15)) * 128 +
                                                        kb + (lane >> 4) * 16));
                ldsm_x4(ah[mi], sb + A_HI + off);
                ldsm_x4(al[mi], sb + A_LO + off);
            }
            uint32_t bh[2][4];
            #pragma unroll
            for (int pi = 0; pi < 2; ++pi) {
                const int q = lane >> 3;
                uint32_t off = ksubB + sw128((uint32_t)(
                    (wn0 + pi * 16 + ((q >> 1) << 3) + (lane & 7)) * 128 +
                    kb + (q & 1) * 16));
                ldsm_x4(bh[pi], sb + B_OF + off);
            }
            #pragma unroll
            for (int mi = 0; mi < 2; ++mi) {
                #pragma unroll
                for (int pi = 0; pi < 2; ++pi) {
                    #pragma unroll
                    for (int hh = 0; hh < 2; ++hh) {
                        float* c = acc[mi][pi * 2 + hh];
                        mma_f16(c, ah[mi], bh[pi][2 * hh], bh[pi][2 * hh + 1]);
                        mma_f16(c, al[mi], bh[pi][2 * hh], bh[pi][2 * hh + 1]);
                    }
                }
            }
        }

        if (t == 0) {
            // all warps finished reading B tile0
            __syncthreads();
            // prefetch B tile1 while we do the epilogue stores
            #pragma unroll
            for (int u = tid; u < 2048; u += 256) {
                int r = u >> 4, g = u & 15;
                int sub = g >> 3, gi = g & 7;
                const __half* src = bmat + (size_t)(128 + r) * K + g * 8;
                cp16(sb + B_OF + sub * 16384 + sw128((uint32_t)(r * 128 + gi * 16)),
                     src, 16u);
            }
        }

        // ---- epilogue for this tile ----
        const int nbase = t * 128;
        #pragma unroll
        for (int mi = 0; mi < 2; ++mi) {
            #pragma unroll
            for (int ni = 0; ni < 4; ++ni) {
                int col = nbase + wn0 + ni * 8 + (lane & 3) * 2;
                int rbase = row0 + wm0 + mi * 16 + (lane >> 2);
                float2 bb = *reinterpret_cast<const float2*>(bias + col);
                #pragma unroll
                for (int p = 0; p < 2; ++p) {
                    int row = rbase + p * 8;
                    if (row >= N_NODES) continue;
                    float v0 = fmaxf(acc[mi][ni][2 * p]     + bb.x, 0.f);
                    float v1 = fmaxf(acc[mi][ni][2 * p + 1] + bb.y, 0.f);
                    float h0 = __half2float(__float2half_rn(v0));
                    float h1 = __half2float(__float2half_rn(v1));
                    *reinterpret_cast<uint32_t*>(o_hi + (size_t)row * D_HID + col) =
                        pack2h(h0, h1);
                    *reinterpret_cast<uint32_t*>(o_lo + (size_t)row * D_HID + col) =
                        pack2h(v0 - h0, v1 - h1);
                }
            }
        }

        if (t == 0) {
            cp_commit_wait();
            __syncthreads();
        }
    }
}

// ---------------------------------------------------------------------------
// GEMM2: block 64x128, warp 32x32, K=256 in 2 chunks, A hi/lo via cp.async.
// ---------------------------------------------------------------------------
__global__ __launch_bounds__(256, 3) void gemm2_kernel(
    const __half* __restrict__ a_hi,
    const __half* __restrict__ a_lo,
    const __half* __restrict__ bmat,   // [128,256] K-major
    const float* __restrict__ bias,
    float* __restrict__ o_f32)
{
    constexpr int K = D_HID;
    constexpr uint32_t A_HI = 0, A_LO = 16384, B_OF = 32768;

    extern __shared__ char smem[];
    const uint32_t sb = smem_u32(smem);

    const int tid  = threadIdx.x;
    const int lane = tid & 31;
    const int wid  = tid >> 5;
    const int wm0  = (wid >> 2) * 32;
    const int wn0  = (wid & 3) * 32;
    const int row0 = blockIdx.x * 64;

    float acc[2][4][4];
    #pragma unroll
    for (int i = 0; i < 2; ++i)
        #pragma unroll
        for (int j = 0; j < 4; ++j)
            #pragma unroll
            for (int q = 0; q < 4; ++q) acc[i][j][q] = 0.f;

    for (int kc = 0; kc < 2; ++kc) {
        #pragma unroll
        for (int u = tid; u < 2048; u += 256) {
            int r = u >> 4, g = u & 15;
            int sub = g >> 3, gi = g & 7;
            const __half* src = bmat + (size_t)r * K + kc * 128 + g * 8;
            cp16(sb + B_OF + sub * 16384 + sw128((uint32_t)(r * 128 + gi * 16)),
                 src, 16u);
        }
        #pragma unroll
        for (int u = tid; u < 2048; u += 256) {
            int buf = u >> 10, rem = u & 1023;
            int r = rem >> 4, g = rem & 15;
            int sub = g >> 3, gi = g & 7;
            int row = row0 + r;
            const __half* src = (buf ? a_lo : a_hi) +
                (size_t)row * K + kc * 128 + g * 8;
            uint32_t off = sub * 8192 + sw128((uint32_t)(r * 128 + gi * 16));
            cp16(sb + (buf ? A_LO : A_HI) + off, src, row < N_NODES ? 16u : 0u);
        }
        cp_commit_wait();
        __syncthreads();

        #pragma unroll
        for (int ks = 0; ks < 8; ++ks) {
            const uint32_t ksubA = (uint32_t)(ks >> 2) * 8192;
            const uint32_t ksubB = (uint32_t)(ks >> 2) * 16384;
            const int kb = (ks & 3) * 32;
            uint32_t ah[2][4], al[2][4];
            #pragma unroll
            for (int mi = 0; mi < 2; ++mi) {
                uint32_t off = ksubA + sw128((uint32_t)((wm0 + mi * 16 + (lane & 15)) * 128 +
                                                        kb + (lane >> 4) * 16));
                ldsm_x4(ah[mi], sb + A_HI + off);
                ldsm_x4(al[mi], sb + A_LO + off);
            }
            uint32_t bh[2][4];
            #pragma unroll
            for (int pi = 0; pi < 2; ++pi) {
                const int q = lane >> 3;
                uint32_t off = ksubB + sw128((uint32_t)(
                    (wn0 + pi * 16 + ((q >> 1) << 3) + (lane & 7)) * 128 +
                    kb + (q & 1) * 16));
                ldsm_x4(bh[pi], sb + B_OF + off);
            }
            #pragma unroll
            for (int mi = 0; mi < 2; ++mi) {
                #pragma unroll
                for (int pi = 0; pi < 2; ++pi) {
                    #pragma unroll
                    for (int hh = 0; hh < 2; ++hh) {
                        float* c = acc[mi][pi * 2 + hh];
                        mma_f16(c, ah[mi], bh[pi][2 * hh], bh[pi][2 * hh + 1]);
                        mma_f16(c, al[mi], bh[pi][2 * hh], bh[pi][2 * hh + 1]);
                    }
                }
            }
        }
        if (kc == 0) __syncthreads();
    }

    #pragma unroll
    for (int mi = 0; mi < 2; ++mi) {
        #pragma unroll
        for (int ni = 0; ni < 4; ++ni) {
            int col = wn0 + ni * 8 + (lane & 3) * 2;
            int rbase = row0 + wm0 + mi * 16 + (lane >> 2);
            float2 bb = *reinterpret_cast<const float2*>(bias + col);
            #pragma unroll
            for (int p = 0; p < 2; ++p) {
                int row = rbase + p * 8;
                if (row >= N_NODES) continue;
                float v0 = acc[mi][ni][2 * p]     + bb.x;
                float v1 = acc[mi][ni][2 * p + 1] + bb.y;
                *reinterpret_cast<float2*>(o_f32 + (size_t)row * D_OUT + col) =
                    make_float2(v0, v1);
            }
        }
    }
}

// ---------------------------------------------------------------------------
// Launch. Inputs: x, edge_src, edge_dst, edge_val, eps, w1, b1, w2, b2
// ---------------------------------------------------------------------------
extern "C" void kernel_launch(void* const* d_in, const int* in_sizes, int n_in,
                              void* d_out, int out_size)
{
    const float* x        = (const float*)d_in[0];
    const int*   edge_src = (const int*)  d_in[1];
    const int*   edge_dst = (const int*)  d_in[2];
    const float* edge_val = (const float*)d_in[3];
    const float* eps      = (const float*)d_in[4];
    const float* w1       = (const float*)d_in[5];
    const float* b1       = (const float*)d_in[6];
    const float* w2       = (const float*)d_in[7];
    const float* b2       = (const float*)d_in[8];
    float* out = (float*)d_out;

    float* aggp;
    __half *hid_hi, *hid_lo, *b1h, *b2h;
    cudaGetSymbolAddress((void**)&aggp,   g_agg);
    cudaGetSymbolAddress((void**)&hid_hi, g_hid_hi);
    cudaGetSymbolAddress((void**)&hid_lo, g_hid_lo);
    cudaGetSymbolAddress((void**)&b1h, g_b1h);
    cudaGetSymbolAddress((void**)&b2h, g_b2h);

    // init: agg = (1+eps)x, xh = fp16(x)
    {
        size_t n = (size_t)N_NODES * D_IN / 4;
        init_kernel<<<(int)((n + 255) / 256), 256>>>(x, eps);
    }
    // aggregation (fp16 gather)
    {
        int warps = (N_EDGES + EDGES_PER_WARP - 1) / EDGES_PER_WARP;
        agg_kernel<<<(warps * 32 + 255) / 256, 256>>>(edge_src, edge_dst, edge_val);
    }
    // weight transpose -> fp16
    conv_b_kernel<<<(D_HID * D_IN + D_OUT * D_HID + 255) / 256, 256>>>(w1, w2);

    const int grid_m = (N_NODES + 63) / 64;
    constexpr int SMEM = 65536;

    // GEMM1: 64x256 per CTA, A staged once
    {
        cudaFuncSetAttribute(gemm1_kernel, cudaFuncAttributeMaxDynamicSharedMemorySize, SMEM);
        gemm1_kernel<<<grid_m, 256, SMEM>>>(aggp, b1h, b1, hid_hi, hid_lo);
    }
    // GEMM2
    {
        cudaFuncSetAttribute(gemm2_kernel, cudaFuncAttributeMaxDynamicSharedMemorySize, SMEM);
        gemm2_kernel<<<grid_m, 256, SMEM>>>(hid_hi, hid_lo, b2h, b2, out);
    }
}

// round 9
// speedup vs baseline: 1.1473x; 1.0589x over previous
#include <cuda_runtime.h>
#include <cuda_fp16.h>
#include <cstdint>

#define N_NODES 50000
#define N_EDGES 800000
#define D_IN    128
#define D_HID   256
#define D_OUT   128
#define NTILES  782          // ceil(50000/64)
#define PGRID   148          // persistent grid (1 CTA/SM)

// ---------------------------------------------------------------------------
// Device scratch
// ---------------------------------------------------------------------------
__device__ float  g_agg   [(size_t)N_NODES * D_IN];
__device__ __half g_xh    [(size_t)N_NODES * D_IN];
__device__ __half g_hid_hi[(size_t)N_NODES * D_HID];
__device__ __half g_hid_lo[(size_t)N_NODES * D_HID];
__device__ __half g_b1h   [D_HID * D_IN];    // w1^T fp16 [256,128]
__device__ __half g_b2h   [D_OUT * D_HID];   // w2^T fp16 [128,256]

// ---------------------------------------------------------------------------
// helpers
// ---------------------------------------------------------------------------
__device__ __forceinline__ uint32_t smem_u32(const void* p) {
    uint32_t a;
    asm("{ .reg .u64 t; cvta.to.shared.u64 t, %1; cvt.u32.u64 %0, t; }" : "=r"(a) : "l"(p));
    return a;
}
__device__ __forceinline__ uint32_t sw128(uint32_t off) { return off ^ ((off >> 3) & 0x70); }

__device__ __forceinline__ uint32_t pack2h(float a, float b) {
    __half2 h = __floats2half2_rn(a, b);
    return *reinterpret_cast<uint32_t*>(&h);
}
__device__ __forceinline__ void ldsm_x4(uint32_t* r, uint32_t addr) {
    asm volatile("ldmatrix.sync.aligned.m8n8.x4.shared.b16 {%0,%1,%2,%3}, [%4];"
                 : "=r"(r[0]), "=r"(r[1]), "=r"(r[2]), "=r"(r[3]) : "r"(addr));
}
__device__ __forceinline__ void mma_f16(float* c, const uint32_t* a, uint32_t b0, uint32_t b1) {
    asm volatile("mma.sync.aligned.m16n8k16.row.col.f32.f16.f16.f32 "
                 "{%0,%1,%2,%3}, {%4,%5,%6,%7}, {%8,%9}, {%0,%1,%2,%3};"
                 : "+f"(c[0]), "+f"(c[1]), "+f"(c[2]), "+f"(c[3])
                 : "r"(a[0]), "r"(a[1]), "r"(a[2]), "r"(a[3]), "r"(b0), "r"(b1));
}
__device__ __forceinline__ void sts16(uint32_t addr, uint4 v) {
    asm volatile("st.shared.v4.b32 [%0], {%1,%2,%3,%4};"
                 :: "r"(addr), "r"(v.x), "r"(v.y), "r"(v.z), "r"(v.w) : "memory");
}
__device__ __forceinline__ void cp16(uint32_t dst, const void* src, uint32_t sz) {
    asm volatile("cp.async.cg.shared.global [%0], [%1], 16, %2;"
                 :: "r"(dst), "l"(src), "r"(sz) : "memory");
}
__device__ __forceinline__ void cp_commit() {
    asm volatile("cp.async.commit_group;" ::: "memory");
}
__device__ __forceinline__ void cp_wait0() {
    asm volatile("cp.async.wait_group 0;" ::: "memory");
}

// ---------------------------------------------------------------------------
// init: agg = (1+eps)*x  AND  xh = fp16(x)
// ---------------------------------------------------------------------------
__global__ void init_kernel(const float* __restrict__ x,
                            const float* __restrict__ eps) {
    const float epsv = 1.0f + eps[0];
    size_t i = (size_t)blockIdx.x * blockDim.x + threadIdx.x;
    size_t n = (size_t)N_NODES * D_IN / 4;
    if (i < n) {
        float4 v = reinterpret_cast<const float4*>(x)[i];
        uint2 h;
        h.x = pack2h(v.x, v.y);
        h.y = pack2h(v.z, v.w);
        reinterpret_cast<uint2*>(g_xh)[i] = h;
        v.x *= epsv; v.y *= epsv; v.z *= epsv; v.w *= epsv;
        reinterpret_cast<float4*>(g_agg)[i] = v;
    }
}

// ---------------------------------------------------------------------------
// edge aggregation, unroll-4 with batched gathers (MLP=4).
// N_EDGES divisible by 128 -> all warp ranges full & 16B-aligned.
// ---------------------------------------------------------------------------
#define EDGES_PER_WARP 128

__global__ __launch_bounds__(256) void agg_kernel(
    const int*   __restrict__ edge_src,
    const int*   __restrict__ edge_dst,
    const float* __restrict__ edge_val)
{
    int gtid   = blockIdx.x * blockDim.x + threadIdx.x;
    int warpId = gtid >> 5;
    int lane   = threadIdx.x & 31;

    long start = (long)warpId * EDGES_PER_WARP;
    if (start >= N_EDGES) return;
    long end = start + EDGES_PER_WARP;

    float ax = 0.f, ay = 0.f, az = 0.f, aw = 0.f;
    int cur_dst = edge_dst[start];

    for (long e = start; e < end; e += 4) {
        int4   d4 = *reinterpret_cast<const int4*>(edge_dst + e);
        int4   s4 = *reinterpret_cast<const int4*>(edge_src + e);
        float4 v4 = *reinterpret_cast<const float4*>(edge_val + e);
        // issue 4 independent gathers
        uint2 h0 = *reinterpret_cast<const uint2*>(g_xh + (size_t)s4.x * D_IN + lane * 4);
        uint2 h1 = *reinterpret_cast<const uint2*>(g_xh + (size_t)s4.y * D_IN + lane * 4);
        uint2 h2 = *reinterpret_cast<const uint2*>(g_xh + (size_t)s4.z * D_IN + lane * 4);
        uint2 h3 = *reinterpret_cast<const uint2*>(g_xh + (size_t)s4.w * D_IN + lane * 4);

        #define PROC(dd, vv, hh)                                                   \
        do {                                                                       \
            if ((dd) != cur_dst) {                                                 \
                float* o = g_agg + (size_t)cur_dst * D_IN + lane * 4;              \
                atomicAdd(o + 0, ax); atomicAdd(o + 1, ay);                        \
                atomicAdd(o + 2, az); atomicAdd(o + 3, aw);                        \
                ax = ay = az = aw = 0.f;                                           \
                cur_dst = (dd);                                                    \
            }                                                                      \
            float2 p01 = __half22float2(*reinterpret_cast<__half2*>(&(hh).x));     \
            float2 p23 = __half22float2(*reinterpret_cast<__half2*>(&(hh).y));     \
            ax += (vv) * p01.x; ay += (vv) * p01.y;                                \
            az += (vv) * p23.x; aw += (vv) * p23.y;                                \
        } while (0)

        PROC(d4.x, v4.x, h0);
        PROC(d4.y, v4.y, h1);
        PROC(d4.z, v4.z, h2);
        PROC(d4.w, v4.w, h3);
        #undef PROC
    }
    float* o = g_agg + (size_t)cur_dst * D_IN + lane * 4;
    atomicAdd(o + 0, ax); atomicAdd(o + 1, ay);
    atomicAdd(o + 2, az); atomicAdd(o + 3, aw);
}

// ---------------------------------------------------------------------------
// weight transpose -> fp16
// ---------------------------------------------------------------------------
__global__ __launch_bounds__(256) void conv_b_kernel(const float* __restrict__ w1,
                                                     const float* __restrict__ w2)
{
    int idx = blockIdx.x * blockDim.x + threadIdx.x;
    if (idx < D_HID * D_IN) {
        int n = idx / D_IN, k = idx % D_IN;
        g_b1h[idx] = __float2half_rn(w1[(size_t)k * D_HID + n]);
    }
    int idx2 = idx - D_HID * D_IN;
    if (idx2 >= 0 && idx2 < D_OUT * D_HID) {
        int n = idx2 / D_HID, k = idx2 % D_HID;
        g_b2h[idx2] = __float2half_rn(w2[(size_t)k * D_OUT + n]);
    }
}

// ---------------------------------------------------------------------------
// GEMM1 persistent: B1 (256x128 fp16, 64KB) resident; loop 64-row tiles.
// A = split(g_agg fp32) on the fly; next tile's LDGs overlap current MMAs.
// SMEM: B 64KB | A double buffer 2 x (HI 16KB + LO 16KB) = 128 KB, 1 CTA/SM.
// 8 warps (2 row x 4 col), warp tile 32x32 per N-tile, 2 N-tiles sequential.
// ---------------------------------------------------------------------------
__global__ __launch_bounds__(256, 1) void gemm1_kernel(
    const float* __restrict__ aggp,
    const __half* __restrict__ bmat,
    const float* __restrict__ bias,
    __half* __restrict__ o_hi,
    __half* __restrict__ o_lo)
{
    constexpr int K = D_IN;
    constexpr uint32_t A_BUF = 65536;

    extern __shared__ char smem[];
    const uint32_t sb = smem_u32(smem);

    const int tid  = threadIdx.x;
    const int lane = tid & 31;
    const int wid  = tid >> 5;
    const int wm0  = (wid >> 2) * 32;
    const int wn0  = (wid & 3) * 32;

    // ---- stage resident B (4096 x 16B) ----
    #pragma unroll
    for (int u = tid; u < 4096; u += 256) {
        int r = u >> 4, g = u & 15;
        int nt = r >> 7, rt = r & 127;
        int sub = g >> 3, gi = g & 7;
        const __half* src = bmat + (size_t)r * K + g * 8;
        cp16(sb + nt * 32768 + sub * 16384 + sw128((uint32_t)(rt * 128 + gi * 16)),
             src, 16u);
    }
    cp_commit();

    // ---- prefetch A(tile0) into registers ----
    float ar[32];
    int t = blockIdx.x;
    {
        #pragma unroll
        for (int uu = 0; uu < 4; ++uu) {
            int u = tid + uu * 256;
            int r = u >> 4, g = u & 15;
            int row = t * 64 + r;
            float* d = ar + uu * 8;
            if (row < N_NODES) {
                const float* pa = aggp + (size_t)row * K + g * 8;
                float4 a0 = *reinterpret_cast<const float4*>(pa);
                float4 a1 = *reinterpret_cast<const float4*>(pa + 4);
                d[0] = a0.x; d[1] = a0.y; d[2] = a0.z; d[3] = a0.w;
                d[4] = a1.x; d[5] = a1.y; d[6] = a1.z; d[7] = a1.w;
            } else {
                #pragma unroll
                for (int j = 0; j < 8; ++j) d[j] = 0.f;
            }
        }
    }
    cp_wait0();

    // convert + STS into buf0
    int buf = 0;
    #pragma unroll
    for (int uu = 0; uu < 4; ++uu) {
        int u = tid + uu * 256;
        int r = u >> 4, g = u & 15;
        int sub = g >> 3, gi = g & 7;
        float* v = ar + uu * 8;
        float h[8], l[8];
        #pragma unroll
        for (int j = 0; j < 8; ++j) {
            h[j] = __half2float(__float2half_rn(v[j]));
            l[j] = v[j] - h[j];
        }
        uint32_t off = A_BUF + sub * 8192 + sw128((uint32_t)(r * 128 + gi * 16));
        sts16(sb + off,
              make_uint4(pack2h(h[0], h[1]), pack2h(h[2], h[3]),
                         pack2h(h[4], h[5]), pack2h(h[6], h[7])));
        sts16(sb + off + 16384,
              make_uint4(pack2h(l[0], l[1]), pack2h(l[2], l[3]),
                         pack2h(l[4], l[5]), pack2h(l[6], l[7])));
    }
    __syncthreads();

    while (t < NTILES) {
        const int tn = t + PGRID;
        const bool more = tn < NTILES;
        // ---- prefetch next A into registers (overlaps MMAs below) ----
        if (more) {
            #pragma unroll
            for (int uu = 0; uu < 4; ++uu) {
                int u = tid + uu * 256;
                int r = u >> 4, g = u & 15;
                int row = tn * 64 + r;
                float* d = ar + uu * 8;
                if (row < N_NODES) {
                    const float* pa = aggp + (size_t)row * K + g * 8;
                    float4 a0 = *reinterpret_cast<const float4*>(pa);
                    float4 a1 = *reinterpret_cast<const float4*>(pa + 4);
                    d[0] = a0.x; d[1] = a0.y; d[2] = a0.z; d[3] = a0.w;
                    d[4] = a1.x; d[5] = a1.y; d[6] = a1.z; d[7] = a1.w;
                } else {
                    #pragma unroll
                    for (int j = 0; j < 8; ++j) d[j] = 0.f;
                }
            }
        }

        const uint32_t abase = A_BUF + (uint32_t)buf * 32768;
        const int row0 = t * 64;

        // ---- two N-tiles ----
        #pragma unroll
        for (int nt = 0; nt < 2; ++nt) {
            float acc[2][4][4];
            #pragma unroll
            for (int i = 0; i < 2; ++i)
                #pragma unroll
                for (int j = 0; j < 4; ++j)
                    #pragma unroll
                    for (int q = 0; q < 4; ++q) acc[i][j][q] = 0.f;

            const uint32_t bbase = (uint32_t)nt * 32768;
            #pragma unroll
            for (int ks = 0; ks < 8; ++ks) {
                const uint32_t ksubA = (uint32_t)(ks >> 2) * 8192;
                const uint32_t ksubB = (uint32_t)(ks >> 2) * 16384;
                const int kb = (ks & 3) * 32;
                uint32_t ah[2][4], al[2][4];
                #pragma unroll
                for (int mi = 0; mi < 2; ++mi) {
                    uint32_t off = abase + ksubA +
                        sw128((uint32_t)((wm0 + mi * 16 + (lane & 15)) * 128 +
                                         kb + (lane >> 4) * 16));
                    ldsm_x4(ah[mi], sb + off);
                    ldsm_x4(al[mi], sb + off + 16384);
                }
                uint32_t bh[2][4];
                #pragma unroll
                for (int pi = 0; pi < 2; ++pi) {
                    const int q = lane >> 3;
                    uint32_t off = bbase + ksubB + sw128((uint32_t)(
                        (wn0 + pi * 16 + ((q >> 1) << 3) + (lane & 7)) * 128 +
                        kb + (q & 1) * 16));
                    ldsm_x4(bh[pi], sb + off);
                }
                #pragma unroll
                for (int mi = 0; mi < 2; ++mi)
                    #pragma unroll
                    for (int pi = 0; pi < 2; ++pi)
                        #pragma unroll
                        for (int hh = 0; hh < 2; ++hh) {
                            float* c = acc[mi][pi * 2 + hh];
                            mma_f16(c, ah[mi], bh[pi][2 * hh], bh[pi][2 * hh + 1]);
                            mma_f16(c, al[mi], bh[pi][2 * hh], bh[pi][2 * hh + 1]);
                        }
            }
            // epilogue for this N-tile
            const int nbase = nt * 128;
            #pragma unroll
            for (int mi = 0; mi < 2; ++mi) {
                #pragma unroll
                for (int ni = 0; ni < 4; ++ni) {
                    int col = nbase + wn0 + ni * 8 + (lane & 3) * 2;
                    int rbase = row0 + wm0 + mi * 16 + (lane >> 2);
                    float2 bb = *reinterpret_cast<const float2*>(bias + col);
                    #pragma unroll
                    for (int p = 0; p < 2; ++p) {
                        int row = rbase + p * 8;
                        if (row >= N_NODES) continue;
                        float v0 = fmaxf(acc[mi][ni][2 * p]     + bb.x, 0.f);
                        float v1 = fmaxf(acc[mi][ni][2 * p + 1] + bb.y, 0.f);
                        float h0 = __half2float(__float2half_rn(v0));
                        float h1 = __half2float(__float2half_rn(v1));
                        *reinterpret_cast<uint32_t*>(o_hi + (size_t)row * D_HID + col) =
                            pack2h(h0, h1);
                        *reinterpret_cast<uint32_t*>(o_lo + (size_t)row * D_HID + col) =
                            pack2h(v0 - h0, v1 - h1);
                    }
                }
            }
        }

        // ---- convert + STS next tile into alternate buffer ----
        if (more) {
            const uint32_t nb = A_BUF + (uint32_t)(buf ^ 1) * 32768;
            #pragma unroll
            for (int uu = 0; uu < 4; ++uu) {
                int u = tid + uu * 256;
                int r = u >> 4, g = u & 15;
                int sub = g >> 3, gi = g & 7;
                float* v = ar + uu * 8;
                float h[8], l[8];
                #pragma unroll
                for (int j = 0; j < 8; ++j) {
                    h[j] = __half2float(__float2half_rn(v[j]));
                    l[j] = v[j] - h[j];
                }
                uint32_t off = nb + sub * 8192 + sw128((uint32_t)(r * 128 + gi * 16));
                sts16(sb + off,
                      make_uint4(pack2h(h[0], h[1]), pack2h(h[2], h[3]),
                                 pack2h(h[4], h[5]), pack2h(h[6], h[7])));
                sts16(sb + off + 16384,
                      make_uint4(pack2h(l[0], l[1]), pack2h(l[2], l[3]),
                                 pack2h(l[4], l[5]), pack2h(l[6], l[7])));
            }
        }
        __syncthreads();
        buf ^= 1;
        t = tn;
    }
}

// ---------------------------------------------------------------------------
// GEMM2 persistent: B2 (128x256 fp16, 64KB) resident; A (hid hi/lo) via
// cp.async double buffer. SMEM: B 64KB | A 2 x 64KB = 192 KB, 1 CTA/SM.
// Block 64x128, warp 32x32, K=256 (16 k16 steps).
// ---------------------------------------------------------------------------
__global__ __launch_bounds__(256, 1) void gemm2_kernel(
    const __half* __restrict__ a_hi,
    const __half* __restrict__ a_lo,
    const __half* __restrict__ bmat,
    const float* __restrict__ bias,
    float* __restrict__ o_f32)
{
    constexpr int K = D_HID;
    constexpr uint32_t A_BUF = 65536;

    extern __shared__ char smem[];
    const uint32_t sb = smem_u32(smem);

    const int tid  = threadIdx.x;
    const int lane = tid & 31;
    const int wid  = tid >> 5;
    const int wm0  = (wid >> 2) * 32;
    const int wn0  = (wid & 3) * 32;

    // ---- stage resident B: 4096 units ----
    #pragma unroll
    for (int u = tid; u < 4096; u += 256) {
        int r = u >> 5, g = u & 31;
        int kc = g >> 4, sub = (g >> 3) & 1, gi = g & 7;
        const __half* src = bmat + (size_t)r * K + g * 8;
        cp16(sb + kc * 32768 + sub * 16384 + sw128((uint32_t)(r * 128 + gi * 16)),
             src, 16u);
    }

    // ---- stage A(tile0) into buf0: 4096 units ----
    int t = blockIdx.x;
    auto stage_A = [&](int tile, int buf) {
        const uint32_t base = A_BUF + (uint32_t)buf * 65536;
        #pragma unroll
        for (int u = tid; u < 4096; u += 256) {
            int comp = u >> 11, rem = u & 2047;
            int r = rem >> 5, g = rem & 31;
            int kc = g >> 4, sub = (g >> 3) & 1, gi = g & 7;
            int row = tile * 64 + r;
            const __half* src = (comp ? a_lo : a_hi) + (size_t)row * K + g * 8;
            uint32_t off = base + comp * 32768 + kc * 16384 + sub * 8192 +
                           sw128((uint32_t)(r * 128 + gi * 16));
            cp16(sb + off, src, row < N_NODES ? 16u : 0u);
        }
    };
    stage_A(t, 0);
    cp_commit();
    cp_wait0();
    __syncthreads();

    int buf = 0;
    while (t < NTILES) {
        const int tn = t + PGRID;
        const bool more = tn < NTILES;
        if (more) {
            stage_A(tn, buf ^ 1);
            cp_commit();
        }

        const uint32_t abase = A_BUF + (uint32_t)buf * 65536;
        const int row0 = t * 64;

        float acc[2][4][4];
        #pragma unroll
        for (int i = 0; i < 2; ++i)
            #pragma unroll
            for (int j = 0; j < 4; ++j)
                #pragma unroll
                for (int q = 0; q < 4; ++q) acc[i][j][q] = 0.f;

        #pragma unroll
        for (int ks = 0; ks < 16; ++ks) {
            const int kc = ks >> 3, k7 = ks & 7;
            const uint32_t ksubA = (uint32_t)kc * 16384 + (uint32_t)(k7 >> 2) * 8192;
            const uint32_t ksubB = (uint32_t)kc * 32768 + (uint32_t)(k7 >> 2) * 16384;
            const int kb = (k7 & 3) * 32;
            uint32_t ah[2][4], al[2][4];
            #pragma unroll
            for (int mi = 0; mi < 2; ++mi) {
                uint32_t off = abase + ksubA +
                    sw128((uint32_t)((wm0 + mi * 16 + (lane & 15)) * 128 +
                                     kb + (lane >> 4) * 16));
                ldsm_x4(ah[mi], sb + off);
                ldsm_x4(al[mi], sb + off + 32768);
            }
            uint32_t bh[2][4];
            #pragma unroll
            for (int pi = 0; pi < 2; ++pi) {
                const int q = lane >> 3;
                uint32_t off = ksubB + sw128((uint32_t)(
                    (wn0 + pi * 16 + ((q >> 1) << 3) + (lane & 7)) * 128 +
                    kb + (q & 1) * 16));
                ldsm_x4(bh[pi], sb + off);
            }
            #pragma unroll
            for (int mi = 0; mi < 2; ++mi)
                #pragma unroll
                for (int pi = 0; pi < 2; ++pi)
                    #pragma unroll
                    for (int hh = 0; hh < 2; ++hh) {
                        float* c = acc[mi][pi * 2 + hh];
                        mma_f16(c, ah[mi], bh[pi][2 * hh], bh[pi][2 * hh + 1]);
                        mma_f16(c, al[mi], bh[pi][2 * hh], bh[pi][2 * hh + 1]);
                    }
        }

        // epilogue
        #pragma unroll
        for (int mi = 0; mi < 2; ++mi) {
            #pragma unroll
            for (int ni = 0; ni < 4; ++ni) {
                int col = wn0 + ni * 8 + (lane & 3) * 2;
                int rbase = row0 + wm0 + mi * 16 + (lane >> 2);
                float2 bb = *reinterpret_cast<const float2*>(bias + col);
                #pragma unroll
                for (int p = 0; p < 2; ++p) {
                    int row = rbase + p * 8;
                    if (row >= N_NODES) continue;
                    *reinterpret_cast<float2*>(o_f32 + (size_t)row * D_OUT + col) =
                        make_float2(acc[mi][ni][2 * p] + bb.x,
                                    acc[mi][ni][2 * p + 1] + bb.y);
                }
            }
        }

        cp_wait0();
        __syncthreads();
        buf ^= 1;
        t = tn;
    }
}

// ---------------------------------------------------------------------------
// Launch. Inputs: x, edge_src, edge_dst, edge_val, eps, w1, b1, w2, b2
// ---------------------------------------------------------------------------
extern "C" void kernel_launch(void* const* d_in, const int* in_sizes, int n_in,
                              void* d_out, int out_size)
{
    const float* x        = (const float*)d_in[0];
    const int*   edge_src = (const int*)  d_in[1];
    const int*   edge_dst = (const int*)  d_in[2];
    const float* edge_val = (const float*)d_in[3];
    const float* eps      = (const float*)d_in[4];
    const float* w1       = (const float*)d_in[5];
    const float* b1       = (const float*)d_in[6];
    const float* w2       = (const float*)d_in[7];
    const float* b2       = (const float*)d_in[8];
    float* out = (float*)d_out;

    float* aggp;
    __half *hid_hi, *hid_lo, *b1h, *b2h;
    cudaGetSymbolAddress((void**)&aggp,   g_agg);
    cudaGetSymbolAddress((void**)&hid_hi, g_hid_hi);
    cudaGetSymbolAddress((void**)&hid_lo, g_hid_lo);
    cudaGetSymbolAddress((void**)&b1h, g_b1h);
    cudaGetSymbolAddress((void**)&b2h, g_b2h);

    {
        size_t n = (size_t)N_NODES * D_IN / 4;
        init_kernel<<<(int)((n + 255) / 256), 256>>>(x, eps);
    }
    {
        int warps = (N_EDGES + EDGES_PER_WARP - 1) / EDGES_PER_WARP;
        agg_kernel<<<(warps * 32 + 255) / 256, 256>>>(edge_src, edge_dst, edge_val);
    }
    conv_b_kernel<<<(D_HID * D_IN + D_OUT * D_HID + 255) / 256, 256>>>(w1, w2);

    {
        constexpr int SMEM1 = 131072;   // B 64K + A 2x32K
        cudaFuncSetAttribute(gemm1_kernel, cudaFuncAttributeMaxDynamicSharedMemorySize, SMEM1);
        gemm1_kernel<<<PGRID, 256, SMEM1>>>(aggp, b1h, b1, hid_hi, hid_lo);
    }
    {
        constexpr int SMEM2 = 196608;   // B 64K + A 2x64K
        cudaFuncSetAttribute(gemm2_kernel, cudaFuncAttributeMaxDynamicSharedMemorySize, SMEM2);
        gemm2_kernel<<<PGRID, 256, SMEM2>>>(hid_hi, hid_lo, b2h, b2, out);
    }
}

// round 10
// speedup vs baseline: 1.4129x; 1.2315x over previous
#include <cuda_runtime.h>
#include <cuda_fp16.h>
#include <cstdint>

#define N_NODES 50000
#define N_EDGES 800000
#define D_IN    128
#define D_HID   256
#define D_OUT   128
#define NTILES  782
#define PGRID   148

// ---------------------------------------------------------------------------
// Device scratch
// ---------------------------------------------------------------------------
__device__ float  g_agg[(size_t)N_NODES * D_IN];
__device__ __half g_xh [(size_t)N_NODES * D_IN];
__device__ __half g_b1h[D_HID * D_IN];    // w1^T fp16 [256,128]
__device__ __half g_b2h[D_OUT * D_HID];   // w2^T fp16 [128,256]

// ---------------------------------------------------------------------------
// helpers
// ---------------------------------------------------------------------------
__device__ __forceinline__ uint32_t smem_u32(const void* p) {
    uint32_t a;
    asm("{ .reg .u64 t; cvta.to.shared.u64 t, %1; cvt.u32.u64 %0, t; }" : "=r"(a) : "l"(p));
    return a;
}
__device__ __forceinline__ uint32_t sw128(uint32_t off) { return off ^ ((off >> 3) & 0x70); }

__device__ __forceinline__ uint32_t pack2h(float a, float b) {
    __half2 h = __floats2half2_rn(a, b);
    return *reinterpret_cast<uint32_t*>(&h);
}
__device__ __forceinline__ void ldsm_x4(uint32_t* r, uint32_t addr) {
    asm volatile("ldmatrix.sync.aligned.m8n8.x4.shared.b16 {%0,%1,%2,%3}, [%4];"
                 : "=r"(r[0]), "=r"(r[1]), "=r"(r[2]), "=r"(r[3]) : "r"(addr));
}
__device__ __forceinline__ void mma_f16(float* c, const uint32_t* a, uint32_t b0, uint32_t b1) {
    asm volatile("mma.sync.aligned.m16n8k16.row.col.f32.f16.f16.f32 "
                 "{%0,%1,%2,%3}, {%4,%5,%6,%7}, {%8,%9}, {%0,%1,%2,%3};"
                 : "+f"(c[0]), "+f"(c[1]), "+f"(c[2]), "+f"(c[3])
                 : "r"(a[0]), "r"(a[1]), "r"(a[2]), "r"(a[3]), "r"(b0), "r"(b1));
}
__device__ __forceinline__ void sts16(uint32_t addr, uint4 v) {
    asm volatile("st.shared.v4.b32 [%0], {%1,%2,%3,%4};"
                 :: "r"(addr), "r"(v.x), "r"(v.y), "r"(v.z), "r"(v.w) : "memory");
}
__device__ __forceinline__ void sts4(uint32_t addr, uint32_t v) {
    asm volatile("st.shared.b32 [%0], %1;" :: "r"(addr), "r"(v) : "memory");
}
__device__ __forceinline__ void cp16(uint32_t dst, const void* src, uint32_t sz) {
    asm volatile("cp.async.cg.shared.global [%0], [%1], 16, %2;"
                 :: "r"(dst), "l"(src), "r"(sz) : "memory");
}
__device__ __forceinline__ void cp_commit() { asm volatile("cp.async.commit_group;" ::: "memory"); }
__device__ __forceinline__ void cp_wait0()  { asm volatile("cp.async.wait_group 0;" ::: "memory"); }

// ---------------------------------------------------------------------------
// init: agg = (1+eps)*x  AND  xh = fp16(x)
// ---------------------------------------------------------------------------
__global__ void init_kernel(const float* __restrict__ x,
                            const float* __restrict__ eps) {
    const float epsv = 1.0f + eps[0];
    size_t i = (size_t)blockIdx.x * blockDim.x + threadIdx.x;
    size_t n = (size_t)N_NODES * D_IN / 4;
    if (i < n) {
        float4 v = reinterpret_cast<const float4*>(x)[i];
        uint2 h;
        h.x = pack2h(v.x, v.y);
        h.y = pack2h(v.z, v.w);
        reinterpret_cast<uint2*>(g_xh)[i] = h;
        v.x *= epsv; v.y *= epsv; v.z *= epsv; v.w *= epsv;
        reinterpret_cast<float4*>(g_agg)[i] = v;
    }
}

// ---------------------------------------------------------------------------
// edge aggregation: unroll-4 batched gathers
// ---------------------------------------------------------------------------
#define EDGES_PER_WARP 128

__global__ __launch_bounds__(256) void agg_kernel(
    const int*   __restrict__ edge_src,
    const int*   __restrict__ edge_dst,
    const float* __restrict__ edge_val)
{
    int gtid   = blockIdx.x * blockDim.x + threadIdx.x;
    int warpId = gtid >> 5;
    int lane   = threadIdx.x & 31;

    long start = (long)warpId * EDGES_PER_WARP;
    if (start >= N_EDGES) return;
    long end = start + EDGES_PER_WARP;

    float ax = 0.f, ay = 0.f, az = 0.f, aw = 0.f;
    int cur_dst = edge_dst[start];

    for (long e = start; e < end; e += 4) {
        int4   d4 = *reinterpret_cast<const int4*>(edge_dst + e);
        int4   s4 = *reinterpret_cast<const int4*>(edge_src + e);
        float4 v4 = *reinterpret_cast<const float4*>(edge_val + e);
        uint2 h0 = *reinterpret_cast<const uint2*>(g_xh + (size_t)s4.x * D_IN + lane * 4);
        uint2 h1 = *reinterpret_cast<const uint2*>(g_xh + (size_t)s4.y * D_IN + lane * 4);
        uint2 h2 = *reinterpret_cast<const uint2*>(g_xh + (size_t)s4.z * D_IN + lane * 4);
        uint2 h3 = *reinterpret_cast<const uint2*>(g_xh + (size_t)s4.w * D_IN + lane * 4);

        #define PROC(dd, vv, hh)                                                   \
        do {                                                                       \
            if ((dd) != cur_dst) {                                                 \
                float* o = g_agg + (size_t)cur_dst * D_IN + lane * 4;              \
                atomicAdd(o + 0, ax); atomicAdd(o + 1, ay);                        \
                atomicAdd(o + 2, az); atomicAdd(o + 3, aw);                        \
                ax = ay = az = aw = 0.f;                                           \
                cur_dst = (dd);                                                    \
            }                                                                      \
            float2 p01 = __half22float2(*reinterpret_cast<__half2*>(&(hh).x));     \
            float2 p23 = __half22float2(*reinterpret_cast<__half2*>(&(hh).y));     \
            ax += (vv) * p01.x; ay += (vv) * p01.y;                                \
            az += (vv) * p23.x; aw += (vv) * p23.y;                                \
        } while (0)

        PROC(d4.x, v4.x, h0);
        PROC(d4.y, v4.y, h1);
        PROC(d4.z, v4.z, h2);
        PROC(d4.w, v4.w, h3);
        #undef PROC
    }
    float* o = g_agg + (size_t)cur_dst * D_IN + lane * 4;
    atomicAdd(o + 0, ax); atomicAdd(o + 1, ay);
    atomicAdd(o + 2, az); atomicAdd(o + 3, aw);
}

// ---------------------------------------------------------------------------
// weight transpose -> fp16
// ---------------------------------------------------------------------------
__global__ __launch_bounds__(256) void conv_b_kernel(const float* __restrict__ w1,
                                                     const float* __restrict__ w2)
{
    int idx = blockIdx.x * blockDim.x + threadIdx.x;
    if (idx < D_HID * D_IN) {
        int n = idx / D_IN, k = idx % D_IN;
        g_b1h[idx] = __float2half_rn(w1[(size_t)k * D_HID + n]);
    }
    int idx2 = idx - D_HID * D_IN;
    if (idx2 >= 0 && idx2 < D_OUT * D_HID) {
        int n = idx2 / D_HID, k = idx2 % D_HID;
        g_b2h[idx2] = __float2half_rn(w2[(size_t)k * D_OUT + n]);
    }
}

// ---------------------------------------------------------------------------
// FUSED MLP, persistent. Per 64-row tile:
//   GEMM1 (A=split(agg), B1 resident) -> bias+relu+split -> HID in SMEM
//   GEMM2 (HID, B2 resident) -> bias -> out fp32
// SMEM (224 KB): B1 0..64K | B2 64..128K | HID 128..192K | A 192..224K
// 8 warps (2 row x 4 col), warp tile 32x32. Fragment double-buffered k-loops.
// ---------------------------------------------------------------------------
__global__ __launch_bounds__(256, 1) void fused_kernel(
    const float* __restrict__ aggp,
    const __half* __restrict__ b1mat,
    const __half* __restrict__ b2mat,
    const float* __restrict__ bias1,
    const float* __restrict__ bias2,
    float* __restrict__ out)
{
    constexpr uint32_t B1_OF = 0, B2_OF = 65536, HID_OF = 131072, A_OF = 196608;

    extern __shared__ char smem[];
    const uint32_t sb = smem_u32(smem);

    const int tid  = threadIdx.x;
    const int lane = tid & 31;
    const int wid  = tid >> 5;
    const int wm0  = (wid >> 2) * 32;
    const int wn0  = (wid & 3) * 32;

    // ---- stage resident B1 ----
    #pragma unroll
    for (int u = tid; u < 4096; u += 256) {
        int r = u >> 4, g = u & 15;
        int nt = r >> 7, rt = r & 127;
        int sub = g >> 3, gi = g & 7;
        cp16(sb + B1_OF + nt * 32768 + sub * 16384 + sw128((uint32_t)(rt * 128 + gi * 16)),
             b1mat + (size_t)r * D_IN + g * 8, 16u);
    }
    // ---- stage resident B2 ----
    #pragma unroll
    for (int u = tid; u < 4096; u += 256) {
        int r = u >> 5, g = u & 31;
        int kc = g >> 4, sub = (g >> 3) & 1, gi = g & 7;
        cp16(sb + B2_OF + kc * 32768 + sub * 16384 + sw128((uint32_t)(r * 128 + gi * 16)),
             b2mat + (size_t)r * D_HID + g * 8, 16u);
    }
    cp_commit();

    // ---- A prefetch (tile0) into regs ----
    float ar[32];
    auto lda = [&](int tile) {
        #pragma unroll
        for (int uu = 0; uu < 4; ++uu) {
            int u = tid + uu * 256;
            int r = u >> 4, g = u & 15;
            int row = tile * 64 + r;
            float* d = ar + uu * 8;
            if (row < N_NODES) {
                const float* pa = aggp + (size_t)row * D_IN + g * 8;
                float4 a0 = *reinterpret_cast<const float4*>(pa);
                float4 a1 = *reinterpret_cast<const float4*>(pa + 4);
                d[0] = a0.x; d[1] = a0.y; d[2] = a0.z; d[3] = a0.w;
                d[4] = a1.x; d[5] = a1.y; d[6] = a1.z; d[7] = a1.w;
            } else {
                #pragma unroll
                for (int j = 0; j < 8; ++j) d[j] = 0.f;
            }
        }
    };
    auto sta = [&]() {   // convert ar -> split fp16 -> A_OF
        #pragma unroll
        for (int uu = 0; uu < 4; ++uu) {
            int u = tid + uu * 256;
            int r = u >> 4, g = u & 15;
            int sub = g >> 3, gi = g & 7;
            float* v = ar + uu * 8;
            float h[8], l[8];
            #pragma unroll
            for (int j = 0; j < 8; ++j) {
                h[j] = __half2float(__float2half_rn(v[j]));
                l[j] = v[j] - h[j];
            }
            uint32_t off = A_OF + sub * 8192 + sw128((uint32_t)(r * 128 + gi * 16));
            sts16(sb + off,
                  make_uint4(pack2h(h[0], h[1]), pack2h(h[2], h[3]),
                             pack2h(h[4], h[5]), pack2h(h[6], h[7])));
            sts16(sb + off + 16384,
                  make_uint4(pack2h(l[0], l[1]), pack2h(l[2], l[3]),
                             pack2h(l[4], l[5]), pack2h(l[6], l[7])));
        }
    };

    int t = blockIdx.x;
    lda(t);
    cp_wait0();
    sta();
    __syncthreads();

    while (t < NTILES) {
        const int tn = t + PGRID;
        const bool more = tn < NTILES;
        if (more) lda(tn);   // overlaps GEMM1 MMAs

        const int row0 = t * 64;

        // ================= GEMM1: 2 N-tiles over resident B1 =================
        #pragma unroll
        for (int nt = 0; nt < 2; ++nt) {
            float acc[2][4][4];
            #pragma unroll
            for (int i = 0; i < 2; ++i)
                #pragma unroll
                for (int j = 0; j < 4; ++j)
                    #pragma unroll
                    for (int q = 0; q < 4; ++q) acc[i][j][q] = 0.f;

            const uint32_t bbase = B1_OF + (uint32_t)nt * 32768;
            uint32_t ahf[2][2][4], alf[2][2][4], bhf[2][2][4];

            auto ld1 = [&](int ks, int slot) {
                const uint32_t ksubA = (uint32_t)(ks >> 2) * 8192;
                const uint32_t ksubB = (uint32_t)(ks >> 2) * 16384;
                const int kb = (ks & 3) * 32;
                #pragma unroll
                for (int mi = 0; mi < 2; ++mi) {
                    uint32_t off = A_OF + ksubA +
                        sw128((uint32_t)((wm0 + mi * 16 + (lane & 15)) * 128 +
                                         kb + (lane >> 4) * 16));
                    ldsm_x4(ahf[slot][mi], sb + off);
                    ldsm_x4(alf[slot][mi], sb + off + 16384);
                }
                #pragma unroll
                for (int pi = 0; pi < 2; ++pi) {
                    const int q = lane >> 3;
                    uint32_t off = bbase + ksubB + sw128((uint32_t)(
                        (wn0 + pi * 16 + ((q >> 1) << 3) + (lane & 7)) * 128 +
                        kb + (q & 1) * 16));
                    ldsm_x4(bhf[slot][pi], sb + off);
                }
            };
            ld1(0, 0);
            #pragma unroll
            for (int ks = 0; ks < 8; ++ks) {
                const int cur = ks & 1;
                if (ks < 7) ld1(ks + 1, cur ^ 1);
                #pragma unroll
                for (int mi = 0; mi < 2; ++mi)
                    #pragma unroll
                    for (int pi = 0; pi < 2; ++pi)
                        #pragma unroll
                        for (int hh = 0; hh < 2; ++hh) {
                            float* c = acc[mi][pi * 2 + hh];
                            mma_f16(c, ahf[cur][mi], bhf[cur][pi][2 * hh], bhf[cur][pi][2 * hh + 1]);
                            mma_f16(c, alf[cur][mi], bhf[cur][pi][2 * hh], bhf[cur][pi][2 * hh + 1]);
                        }
            }

            // epilogue: bias + relu + split -> HID smem
            #pragma unroll
            for (int mi = 0; mi < 2; ++mi) {
                #pragma unroll
                for (int ni = 0; ni < 4; ++ni) {
                    int colb = nt * 128 + wn0 + ni * 8 + (lane & 3) * 2;
                    float2 bb = *reinterpret_cast<const float2*>(bias1 + colb);
                    int kc = colb >> 7, sub = (colb >> 6) & 1, ci = (colb & 63) * 2;
                    #pragma unroll
                    for (int p = 0; p < 2; ++p) {
                        int r = wm0 + mi * 16 + (lane >> 2) + p * 8;
                        float v0 = fmaxf(acc[mi][ni][2 * p]     + bb.x, 0.f);
                        float v1 = fmaxf(acc[mi][ni][2 * p + 1] + bb.y, 0.f);
                        float h0 = __half2float(__float2half_rn(v0));
                        float h1 = __half2float(__float2half_rn(v1));
                        uint32_t off = HID_OF + kc * 16384 + sub * 8192 +
                                       sw128((uint32_t)(r * 128 + ci));
                        sts4(sb + off,         pack2h(h0, h1));
                        sts4(sb + off + 32768, pack2h(v0 - h0, v1 - h1));
                    }
                }
            }
        }
        __syncthreads();   // HID visible; A reads done

        if (more) sta();   // STS next A (A unused by GEMM2); LSU overlaps MMAs

        // ================= GEMM2: HID (smem) x resident B2 =================
        {
            float acc[2][4][4];
            #pragma unroll
            for (int i = 0; i < 2; ++i)
                #pragma unroll
                for (int j = 0; j < 4; ++j)
                    #pragma unroll
                    for (int q = 0; q < 4; ++q) acc[i][j][q] = 0.f;

            uint32_t ahf[2][2][4], alf[2][2][4], bhf[2][2][4];
            auto ld2 = [&](int ks, int slot) {
                const int kc = ks >> 3, k7 = ks & 7;
                const uint32_t ksubA = (uint32_t)kc * 16384 + (uint32_t)(k7 >> 2) * 8192;
                const uint32_t ksubB = (uint32_t)kc * 32768 + (uint32_t)(k7 >> 2) * 16384;
                const int kb = (k7 & 3) * 32;
                #pragma unroll
                for (int mi = 0; mi < 2; ++mi) {
                    uint32_t off = HID_OF + ksubA +
                        sw128((uint32_t)((wm0 + mi * 16 + (lane & 15)) * 128 +
                                         kb + (lane >> 4) * 16));
                    ldsm_x4(ahf[slot][mi], sb + off);
                    ldsm_x4(alf[slot][mi], sb + off + 32768);
                }
                #pragma unroll
                for (int pi = 0; pi < 2; ++pi) {
                    const int q = lane >> 3;
                    uint32_t off = B2_OF + ksubB + sw128((uint32_t)(
                        (wn0 + pi * 16 + ((q >> 1) << 3) + (lane & 7)) * 128 +
                        kb + (q & 1) * 16));
                    ldsm_x4(bhf[slot][pi], sb + off);
                }
            };
            ld2(0, 0);
            #pragma unroll
            for (int ks = 0; ks < 16; ++ks) {
                const int cur = ks & 1;
                if (ks < 15) ld2(ks + 1, cur ^ 1);
                #pragma unroll
                for (int mi = 0; mi < 2; ++mi)
                    #pragma unroll
                    for (int pi = 0; pi < 2; ++pi)
                        #pragma unroll
                        for (int hh = 0; hh < 2; ++hh) {
                            float* c = acc[mi][pi * 2 + hh];
                            mma_f16(c, ahf[cur][mi], bhf[cur][pi][2 * hh], bhf[cur][pi][2 * hh + 1]);
                            mma_f16(c, alf[cur][mi], bhf[cur][pi][2 * hh], bhf[cur][pi][2 * hh + 1]);
                        }
            }

            // epilogue -> out fp32
            #pragma unroll
            for (int mi = 0; mi < 2; ++mi) {
                #pragma unroll
                for (int ni = 0; ni < 4; ++ni) {
                    int col = wn0 + ni * 8 + (lane & 3) * 2;
                    int rbase = row0 + wm0 + mi * 16 + (lane >> 2);
                    float2 bb = *reinterpret_cast<const float2*>(bias2 + col);
                    #pragma unroll
                    for (int p = 0; p < 2; ++p) {
                        int row = rbase + p * 8;
                        if (row >= N_NODES) continue;
                        *reinterpret_cast<float2*>(out + (size_t)row * D_OUT + col) =
                            make_float2(acc[mi][ni][2 * p] + bb.x,
                                        acc[mi][ni][2 * p + 1] + bb.y);
                    }
                }
            }
        }
        __syncthreads();   // HID/A reuse safe next iteration
        t = tn;
    }
}

// ---------------------------------------------------------------------------
// Launch. Inputs: x, edge_src, edge_dst, edge_val, eps, w1, b1, w2, b2
// ---------------------------------------------------------------------------
extern "C" void kernel_launch(void* const* d_in, const int* in_sizes, int n_in,
                              void* d_out, int out_size)
{
    const float* x        = (const float*)d_in[0];
    const int*   edge_src = (const int*)  d_in[1];
    const int*   edge_dst = (const int*)  d_in[2];
    const float* edge_val = (const float*)d_in[3];
    const float* eps      = (const float*)d_in[4];
    const float* w1       = (const float*)d_in[5];
    const float* b1       = (const float*)d_in[6];
    const float* w2       = (const float*)d_in[7];
    const float* b2       = (const float*)d_in[8];
    float* out = (float*)d_out;

    float* aggp;
    __half *b1h, *b2h;
    cudaGetSymbolAddress((void**)&aggp, g_agg);
    cudaGetSymbolAddress((void**)&b1h,  g_b1h);
    cudaGetSymbolAddress((void**)&b2h,  g_b2h);

    {
        size_t n = (size_t)N_NODES * D_IN / 4;
        init_kernel<<<(int)((n + 255) / 256), 256>>>(x, eps);
    }
    {
        int warps = (N_EDGES + EDGES_PER_WARP - 1) / EDGES_PER_WARP;
        agg_kernel<<<(warps * 32 + 255) / 256, 256>>>(edge_src, edge_dst, edge_val);
    }
    conv_b_kernel<<<(D_HID * D_IN + D_OUT * D_HID + 255) / 256, 256>>>(w1, w2);

    {
        constexpr int SMEM = 229376;   // 224 KB
        cudaFuncSetAttribute(fused_kernel, cudaFuncAttributeMaxDynamicSharedMemorySize, SMEM);
        fused_kernel<<<PGRID, 256, SMEM>>>(aggp, b1h, b2h, b1, b2, out);
    }
}